// round 10
// baseline (speedup 1.0000x reference)
#include <cuda_runtime.h>
#include <cuda_fp16.h>
#include <cstddef>
#include <cstdint>

#define BB 256
#define PP 256
#define VV 5000
#define TT 96
#define GG 2048
#define VPAD 5120
#define SMEMSZ 65536

// ---------------- scratch ----------------
__device__ __half g_att1[(size_t)BB * PP * 512];
__device__ __half g_encb[(size_t)BB * PP * 256];
__device__ __half g_embW16[(size_t)VV * GG];      // fp16 emb@wih_top
__device__ __half g_emb16[(size_t)VV * 256];
__device__ __half g_hall[(size_t)BB * TT * 512];  // t-major
__device__ __half g_xh[BB * 768];                 // [xg | h]
__device__ float  g_h0[BB * 512];
__device__ float  g_c[2 * BB * 512];
__device__ float  g_ag[BB * 768];
__device__ float  g_gates[BB * GG];
__device__ __half g_mean16[BB * 256];
__device__ float  g_bag[768];
// fp16 weights, row-major [k][n]
__device__ __half g_wag[512 * 768];     // [dec_att_w | f_beta_w]
__device__ __half g_whh16[512 * GG];
__device__ __half g_wx16[256 * GG];     // wih rows 256..511
__device__ __half g_wtop16[256 * GG];   // wih rows 0..255
__device__ __half g_wfc[512 * VPAD];
__device__ __half g_wenc[256 * 512];
__device__ __half g_wih0[256 * 512];
__device__ __half g_wic0[256 * 512];

__device__ __forceinline__ float sigmoidf(float x) { return 1.f / (1.f + expf(-x)); }
__device__ __forceinline__ uint32_t su32(const void* p) {
    return (uint32_t)__cvta_generic_to_shared(p);
}
__device__ __forceinline__ void cp16(void* d, const void* s) {
    asm volatile("cp.async.cg.shared.global [%0], [%1], 16;" :: "r"(su32(d)), "l"(s));
}
__device__ __forceinline__ void cpc() { asm volatile("cp.async.commit_group;"); }
template<int N> __device__ __forceinline__ void cpw() {
    asm volatile("cp.async.wait_group %0;" :: "n"(N));
}
__device__ __forceinline__ void ldm_x4(uint32_t* r, uint32_t a) {
    asm volatile("ldmatrix.sync.aligned.m8n8.x4.shared.b16 {%0,%1,%2,%3}, [%4];"
                 : "=r"(r[0]), "=r"(r[1]), "=r"(r[2]), "=r"(r[3]) : "r"(a));
}
__device__ __forceinline__ void ldm_x4_t(uint32_t* r, uint32_t a) {
    asm volatile("ldmatrix.sync.aligned.m8n8.x4.trans.shared.b16 {%0,%1,%2,%3}, [%4];"
                 : "=r"(r[0]), "=r"(r[1]), "=r"(r[2]), "=r"(r[3]) : "r"(a));
}
__device__ __forceinline__ void mma16816(float* c, const uint32_t* a, const uint32_t* b) {
    asm volatile("mma.sync.aligned.m16n8k16.row.col.f32.f16.f16.f32 "
                 "{%0,%1,%2,%3},{%4,%5,%6,%7},{%8,%9},{%0,%1,%2,%3};"
                 : "+f"(c[0]), "+f"(c[1]), "+f"(c[2]), "+f"(c[3])
                 : "r"(a[0]), "r"(a[1]), "r"(a[2]), "r"(a[3]), "r"(b[0]), "r"(b[1]));
}

// ============ 128x128 HMMA tile, 2-stage cp.async (256 threads) ============
__device__ __forceinline__ void tile128(
    __half* sm, const __half* __restrict__ A, int lda,
    const __half* __restrict__ W, int ldw,
    int m0, int n0, int K, int Mclamp, float acc[4][4][4])
{
    __half* As = sm;
    __half* Bs = sm + 16384;
    const int tid = threadIdx.x;
    const int warp = tid >> 5, lane = tid & 31;
    const int wm = (warp & 1) * 64, wn = (warp >> 1) * 32;
#pragma unroll
    for (int i = 0; i < 4; i++)
#pragma unroll
        for (int j = 0; j < 4; j++)
#pragma unroll
            for (int k = 0; k < 4; k++) acc[i][j][k] = 0.f;
    const int nk = K >> 6;

#define TLA(st, kc)                                                             \
    {                                                                           \
        _Pragma("unroll")                                                       \
        for (int i = 0; i < 4; i++) {                                           \
            int idx = tid + i * 256, r = idx >> 3, c = idx & 7;                 \
            int gm = m0 + r; if (gm >= Mclamp) gm = Mclamp - 1;                 \
            cp16(As + (st) * 8192 + r * 64 + (((c ^ r) & 7) << 3),              \
                 A + (size_t)gm * lda + (kc) + c * 8);                          \
        }                                                                       \
    }
#define TLB(st, kc)                                                             \
    {                                                                           \
        _Pragma("unroll")                                                       \
        for (int i = 0; i < 4; i++) {                                           \
            int idx = tid + i * 256, r = idx >> 4, c = idx & 15;                \
            int sw = (c & 8) | ((c ^ r) & 7);                                   \
            cp16(Bs + (st) * 8192 + r * 128 + (sw << 3),                        \
                 W + (size_t)((kc) + r) * ldw + n0 + c * 8);                    \
        }                                                                       \
    }
    TLA(0, 0); TLB(0, 0); cpc();
    for (int k = 0; k < nk; k++) {
        int cur = k & 1;
        if (k + 1 < nk) { TLA(cur ^ 1, (k + 1) * 64); TLB(cur ^ 1, (k + 1) * 64);
                          cpc(); cpw<1>(); }
        else cpw<0>();
        __syncthreads();
        const __half* Ab = As + cur * 8192;
        const __half* Bb = Bs + cur * 8192;
#pragma unroll
        for (int ks = 0; ks < 4; ks++) {
            uint32_t a[4][4], b[2][4];
#pragma unroll
            for (int mi = 0; mi < 4; mi++) {
                int m = wm + mi * 16 + (lane & 15);
                int kch = ks * 2 + (lane >> 4);
                ldm_x4(a[mi], su32(Ab + m * 64 + (((kch ^ m) & 7) << 3)));
            }
#pragma unroll
            for (int ni = 0; ni < 2; ni++) {
                int kk = ks * 16 + (lane & 15);
                int nch = (wn >> 3) + ni * 2 + (lane >> 4);
                int sw = (nch & 8) | ((nch ^ kk) & 7);
                ldm_x4_t(b[ni], su32(Bb + kk * 128 + (sw << 3)));
            }
#pragma unroll
            for (int mi = 0; mi < 4; mi++)
#pragma unroll
                for (int ni = 0; ni < 4; ni++)
                    mma16816(acc[mi][ni], a[mi], &b[ni >> 1][(ni & 1) * 2]);
        }
        __syncthreads();
    }
#undef TLA
#undef TLB
}

// variadic: comma-safe macro body
#define EPI_LOOP(...)                                                           \
    {                                                                           \
        const int warp = threadIdx.x >> 5, lane = threadIdx.x & 31;             \
        const int wm = (warp & 1) * 64, wn = (warp >> 1) * 32;                  \
        _Pragma("unroll")                                                       \
        for (int mi = 0; mi < 4; mi++)                                          \
        _Pragma("unroll")                                                       \
        for (int hh = 0; hh < 2; hh++) {                                        \
            int m = m0 + wm + mi * 16 + (lane >> 2) + hh * 8;                   \
            _Pragma("unroll")                                                   \
            for (int ni = 0; ni < 4; ni++)                                      \
            _Pragma("unroll")                                                   \
            for (int j = 0; j < 2; j++) {                                       \
                int n = n0 + wn + ni * 8 + (lane & 3) * 2 + j;                  \
                float v = acc[mi][ni][hh * 2 + j];                              \
                __VA_ARGS__                                                     \
            }                                                                   \
        }                                                                       \
    }

// ============ generic GEMM: MODE 0 fp32+bias | 3 fc | 4 fp16+bias | 5 fp16 clamp ============
template<int MODE>
__global__ __launch_bounds__(256)
void hgemm_k(const __half* __restrict__ A, int lda,
             const __half* __restrict__ W, int ldw,
             const float* __restrict__ bias,
             float* __restrict__ Cf, __half* __restrict__ Ch, int ldc,
             int M, int K, const int* __restrict__ lens, int mbase)
{
    extern __shared__ __half sm[];
    int m0 = blockIdx.y * 128 + (MODE == 3 ? mbase : 0);
    const int n0 = blockIdx.x * 128;
    if (MODE == 3) {
        int tt = m0 >> 8;
        int bmin = m0 & 255;
        if (lens[bmin] <= tt) return;   // lens sorted desc
    }
    float acc[4][4][4];
    tile128(sm, A, lda, W, ldw, m0, n0, K, (MODE == 5 || MODE == 0) ? M : (1 << 30), acc);
    if (MODE == 0) {
        EPI_LOOP(if (m < M) Cf[(size_t)m * ldc + n] = v + bias[n];)
    } else if (MODE == 3) {
        EPI_LOOP(
            int to = m >> 8;
            int bo = m & 255;
            if (lens[bo] > to && n < VV)
                Cf[((size_t)bo * TT + to) * VV + n] = v + bias[n];
        )
    } else if (MODE == 4) {
        EPI_LOOP(Ch[(size_t)m * ldc + n] = __float2half(v + bias[n]);)
    } else {
        EPI_LOOP(if (m < M) Ch[(size_t)m * ldc + n] = __float2half(v);)
    }
}

// ============ K1: AG GEMM (12 tiles) + gates_h GEMM (32 tiles), one launch ============
__global__ __launch_bounds__(256)
void k1_k()
{
    extern __shared__ __half sm[];
    int w = blockIdx.x;
    float acc[4][4][4];
    if (w < 12) {
        int m0 = (w / 6) * 128, n0 = (w % 6) * 128;
        tile128(sm, g_xh + 256, 768, g_wag, 768, m0, n0, 512, 1 << 30, acc);
        EPI_LOOP(
            v += g_bag[n];
            if (n >= 512) v = sigmoidf(v);
            g_ag[m * 768 + n] = v;
        )
    } else {
        int v2 = w - 12;
        int m0 = (v2 / 16) * 128, n0 = (v2 % 16) * 128;
        tile128(sm, g_xh + 256, 768, g_whh16, GG, m0, n0, 512, 1 << 30, acc);
        EPI_LOOP(g_gates[m * GG + n] = v;)
    }
}

// ============ K2: gates += xg @ wih_bot (K=256) + biases + embW16[cap] ============
__global__ __launch_bounds__(256)
void k2_k(const float* __restrict__ bih, const float* __restrict__ bhh,
          const int* __restrict__ caps, int t)
{
    extern __shared__ __half sm[];
    int w = blockIdx.x;
    int m0 = (w / 16) * 128, n0 = (w % 16) * 128;
    float acc[4][4][4];
    tile128(sm, g_xh, 768, g_wx16, GG, m0, n0, 256, 1 << 30, acc);
    EPI_LOOP(
        int eidx = caps[m * TT + t];
        g_gates[m * GG + n] = v + g_gates[m * GG + n] + bih[n] + bhh[n]
                              + __half2float(g_embW16[(size_t)eidx * GG + n]);
    )
}

// ============ small kernels ============
__global__ void cvt_k(const float* __restrict__ src, __half* __restrict__ dst,
                      int rows, int cols, int sld, int dld, int valid)
{
    int n = rows * cols;
    for (int i = blockIdx.x * blockDim.x + threadIdx.x; i < n; i += gridDim.x * blockDim.x) {
        int r = i / cols, c = i - r * cols;
        float v = (c < valid) ? src[(size_t)r * sld + c] : 0.f;
        dst[(size_t)r * dld + c] = __float2half(v);
    }
}
__global__ void mean_k(const float* __restrict__ enc)
{
    int b = blockIdx.x, e = threadIdx.x;
    const float* p = enc + (size_t)b * PP * 256 + e;
    float s = 0.f;
#pragma unroll 8
    for (int pp = 0; pp < PP; pp++) s += p[(size_t)pp * 256];
    g_mean16[b * 256 + e] = __float2half(s * (1.f / PP));
}
__global__ void bag_k(const float* __restrict__ b1, const float* __restrict__ b2)
{
    int i = threadIdx.x + blockIdx.x * blockDim.x;
    if (i < 512) g_bag[i] = b1[i];
    else if (i < 768) g_bag[i] = b2[i - 512];
}
__global__ void h0c_k()
{
    int b = blockIdx.x, d = threadIdx.x;
    g_xh[b * 768 + 256 + d] = __float2half(g_h0[b * 512 + d]);
}
__global__ void lens_k(const int* __restrict__ lens, float* __restrict__ o)
{
    o[threadIdx.x] = (float)lens[threadIdx.x];
}

__global__ __launch_bounds__(256)
void attention_k(const float* __restrict__ wfull, const int* __restrict__ lens,
                 int t, float* __restrict__ alphas_out)
{
    __shared__ float a2[512], wf[512], es[PP], red[32];
    int b = blockIdx.x, tid = threadIdx.x;
    a2[tid] = g_ag[b * 768 + tid]; a2[tid + 256] = g_ag[b * 768 + 256 + tid];
    wf[tid] = wfull[tid]; wf[tid + 256] = wfull[tid + 256];
    __syncthreads();
    int warp = tid >> 5, lane = tid & 31;
    const __half2* a1 = reinterpret_cast<const __half2*>(g_att1 + (size_t)b * PP * 512);
    for (int p = warp; p < PP; p += 8) {
        const __half2* row = a1 + (size_t)p * 256;
        float acc = 0.f;
#pragma unroll
        for (int i = 0; i < 8; i++) {
            int d2 = lane + 32 * i;
            float2 v = __half22float2(row[d2]);
            acc += fmaxf(v.x + a2[2 * d2], 0.f) * wf[2 * d2]
                 + fmaxf(v.y + a2[2 * d2 + 1], 0.f) * wf[2 * d2 + 1];
        }
#pragma unroll
        for (int o = 16; o > 0; o >>= 1) acc += __shfl_xor_sync(~0u, acc, o);
        if (lane == 0) es[p] = acc;
    }
    __syncthreads();
    float e = es[tid], m = e;
#pragma unroll
    for (int o = 16; o > 0; o >>= 1) m = fmaxf(m, __shfl_xor_sync(~0u, m, o));
    if (lane == 0) red[warp] = m;
    __syncthreads();
    if (tid == 0) { float mm = red[0]; for (int w = 1; w < 8; w++) mm = fmaxf(mm, red[w]); red[16] = mm; }
    __syncthreads();
    float ex = expf(e - red[16]), s = ex;
#pragma unroll
    for (int o = 16; o > 0; o >>= 1) s += __shfl_xor_sync(~0u, s, o);
    if (lane == 0) red[warp] = s;
    __syncthreads();
    if (tid == 0) { float ss = 0.f; for (int w = 0; w < 8; w++) ss += red[w]; red[17] = ss; }
    __syncthreads();
    float alpha = ex / red[17];
    es[tid] = alpha;
    alphas_out[((size_t)b * TT + t) * PP + tid] = (lens[b] > t) ? alpha : 0.f;
    __syncthreads();
    const __half* eb = g_encb + (size_t)b * PP * 256;
    float acc = 0.f;
#pragma unroll 8
    for (int p = 0; p < PP; p++) acc += es[p] * __half2float(eb[(size_t)p * 256 + tid]);
    g_xh[b * 768 + tid] = __float2half(g_ag[b * 768 + 512 + tid] * acc);
}

__global__ void cell_k(const float* __restrict__ cold, float* __restrict__ cnew, int t)
{
    int b = blockIdx.x, d = threadIdx.x;
    const float* g = g_gates + (size_t)b * GG;
    float ig = sigmoidf(g[d]), fg = sigmoidf(g[512 + d]);
    float gv = tanhf(g[1024 + d]), og = sigmoidf(g[1536 + d]);
    float c = fg * cold[b * 512 + d] + ig * gv;
    cnew[b * 512 + d] = c;
    __half hh = __float2half(og * tanhf(c));
    g_xh[b * 768 + 256 + d] = hh;
    g_hall[((size_t)t * BB + b) * 512 + d] = hh;
}

// ============ host ============
#define GSA(p, s) cudaGetSymbolAddress((void**)&p, s)
static inline int cgrid(int n) { int g = (n + 255) / 256; return g > 4096 ? 4096 : g; }

extern "C" void kernel_launch(void* const* d_in, const int* in_sizes, int n_in,
                              void* d_out, int out_size)
{
    const float* enc  = (const float*)d_in[0];
    const int*   caps = (const int*)d_in[1];
    const int*   lens = (const int*)d_in[2];
    const float* emb  = (const float*)d_in[3];
    const float* eaw  = (const float*)d_in[4];
    const float* eab  = (const float*)d_in[5];
    const float* daw  = (const float*)d_in[6];
    const float* dab  = (const float*)d_in[7];
    const float* faw  = (const float*)d_in[8];
    const float* wih  = (const float*)d_in[10];
    const float* whh  = (const float*)d_in[11];
    const float* bih  = (const float*)d_in[12];
    const float* bhh  = (const float*)d_in[13];
    const float* ihw  = (const float*)d_in[14];
    const float* ihb  = (const float*)d_in[15];
    const float* icw  = (const float*)d_in[16];
    const float* icb  = (const float*)d_in[17];
    const float* fbw  = (const float*)d_in[18];
    const float* fbb  = (const float*)d_in[19];
    const float* fcw  = (const float*)d_in[20];
    const float* fcb  = (const float*)d_in[21];

    float* out = (float*)d_out;
    float* out_pred = out;
    float* out_lens = out + (size_t)BB * TT * VV;
    float* out_alph = out_lens + BB;

    cudaFuncSetAttribute(hgemm_k<0>, cudaFuncAttributeMaxDynamicSharedMemorySize, SMEMSZ);
    cudaFuncSetAttribute(hgemm_k<3>, cudaFuncAttributeMaxDynamicSharedMemorySize, SMEMSZ);
    cudaFuncSetAttribute(hgemm_k<4>, cudaFuncAttributeMaxDynamicSharedMemorySize, SMEMSZ);
    cudaFuncSetAttribute(hgemm_k<5>, cudaFuncAttributeMaxDynamicSharedMemorySize, SMEMSZ);
    cudaFuncSetAttribute(k1_k, cudaFuncAttributeMaxDynamicSharedMemorySize, SMEMSZ);
    cudaFuncSetAttribute(k2_k, cudaFuncAttributeMaxDynamicSharedMemorySize, SMEMSZ);

    cudaStream_t s2;
    cudaStreamCreateWithFlags(&s2, cudaStreamNonBlocking);
    cudaEvent_t evA[TT / 8], evB[TT / 8];
    for (int i = 0; i < TT / 8; i++) {
        cudaEventCreateWithFlags(&evA[i], cudaEventDisableTiming);
        cudaEventCreateWithFlags(&evB[i], cudaEventDisableTiming);
    }

    cudaMemsetAsync(d_out, 0, (size_t)out_size * sizeof(float));

    __half *p_encb, *p_emb16, *p_mean16, *p_att1, *p_hall, *p_embW16;
    __half *p_wag, *p_whh16, *p_wx16, *p_wtop16, *p_wfc, *p_wenc, *p_wih0, *p_wic0;
    float *p_h0, *p_c;
    GSA(p_encb, g_encb); GSA(p_emb16, g_emb16); GSA(p_mean16, g_mean16);
    GSA(p_att1, g_att1); GSA(p_hall, g_hall); GSA(p_embW16, g_embW16);
    GSA(p_wag, g_wag); GSA(p_whh16, g_whh16); GSA(p_wx16, g_wx16); GSA(p_wtop16, g_wtop16);
    GSA(p_wfc, g_wfc); GSA(p_wenc, g_wenc); GSA(p_wih0, g_wih0); GSA(p_wic0, g_wic0);
    GSA(p_h0, g_h0); GSA(p_c, g_c);

    // conversions (fp32 -> fp16)
    cvt_k<<<cgrid(BB * PP * 256), 256>>>(enc, p_encb, BB * PP, 256, 256, 256, 256);
    cvt_k<<<cgrid(VV * 256), 256>>>(emb, p_emb16, VV, 256, 256, 256, 256);
    cvt_k<<<cgrid(512 * 512), 256>>>(daw, p_wag, 512, 512, 512, 768, 512);
    cvt_k<<<cgrid(512 * 256), 256>>>(fbw, p_wag + 512, 512, 256, 256, 768, 256);
    cvt_k<<<cgrid(512 * GG), 256>>>(whh, p_whh16, 512, GG, GG, GG, GG);
    cvt_k<<<cgrid(256 * GG), 256>>>(wih, p_wtop16, 256, GG, GG, GG, GG);
    cvt_k<<<cgrid(256 * GG), 256>>>(wih + (size_t)256 * GG, p_wx16, 256, GG, GG, GG, GG);
    cvt_k<<<cgrid(512 * VPAD), 256>>>(fcw, p_wfc, 512, VPAD, VV, VPAD, VV);
    cvt_k<<<cgrid(256 * 512), 256>>>(eaw, p_wenc, 256, 512, 512, 512, 512);
    cvt_k<<<cgrid(256 * 512), 256>>>(ihw, p_wih0, 256, 512, 512, 512, 512);
    cvt_k<<<cgrid(256 * 512), 256>>>(icw, p_wic0, 256, 512, 512, 512, 512);
    bag_k<<<3, 256>>>(dab, fbb);
    mean_k<<<BB, 256>>>(enc);

    // one-time GEMMs
    hgemm_k<0><<<dim3(4, 2), 256, SMEMSZ>>>(p_mean16, 256, p_wih0, 512,
        ihb, p_h0, nullptr, 512, BB, 256, nullptr, 0);
    hgemm_k<0><<<dim3(4, 2), 256, SMEMSZ>>>(p_mean16, 256, p_wic0, 512,
        icb, p_c, nullptr, 512, BB, 256, nullptr, 0);
    h0c_k<<<BB, 512>>>();
    hgemm_k<4><<<dim3(4, 512), 256, SMEMSZ>>>(p_encb, 256, p_wenc, 512,
        eab, nullptr, p_att1, 512, BB * PP, 256, nullptr, 0);
    hgemm_k<5><<<dim3(16, 40), 256, SMEMSZ>>>(p_emb16, 256, p_wtop16, GG,
        nullptr, nullptr, p_embW16, GG, VV, 256, nullptr, 0);
    lens_k<<<1, BB>>>(lens, out_lens);

    // timestep loop; fc chunks forked to s2 every 8 steps
    for (int t = 0; t < TT; t++) {
        const float* ccur = p_c + (t & 1) * (BB * 512);
        float*       cnext = p_c + ((t + 1) & 1) * (BB * 512);
        k1_k<<<44, 256, SMEMSZ>>>();
        attention_k<<<BB, 256>>>(faw, lens, t, out_alph);
        k2_k<<<32, 256, SMEMSZ>>>(bih, bhh, caps, t);
        cell_k<<<BB, 512>>>(ccur, cnext, t);

        if ((t & 7) == 7) {
            int c = t >> 3;
            cudaEventRecord(evA[c], 0);
            cudaStreamWaitEvent(s2, evA[c], 0);
            hgemm_k<3><<<dim3(40, 16), 256, SMEMSZ, s2>>>(p_hall, 512, p_wfc, VPAD,
                fcb, out_pred, nullptr, VV, BB * TT, 512, lens, c * 8 * BB);
            cudaEventRecord(evB[c], s2);
        }
    }
    for (int c = 0; c < TT / 8; c++) cudaStreamWaitEvent(0, evB[c], 0);
}

// round 11
// speedup vs baseline: 1.3897x; 1.3897x over previous
#include <cuda_runtime.h>
#include <cuda_fp16.h>
#include <cstddef>
#include <cstdint>

#define BB   256
#define PP   256
#define ENCD 256
#define DECD 512
#define EE   256
#define VV   5000
#define TT   96
#define GG   2048
#define VPAD 5120

#define SMEMSZ 98304   // 3-stage: 3*(128*64 + 64*128) halves = 96 KB

// ---------------- device scratch ----------------
__device__ __half g_att1[(size_t)BB * PP * DECD];
__device__ __half g_encb[(size_t)BB * PP * ENCD];
__device__ float  g_embW[(size_t)VV * GG];
__device__ __half g_emb16[(size_t)VV * EE];
__device__ __half g_hall[(size_t)BB * TT * DECD];   // t-major: [(t*BB+b)*DECD+d]
__device__ __half g_xh[BB * (ENCD + DECD)];         // [xg | h], ld=768
__device__ float  g_h[BB * DECD];
__device__ float  g_c[2 * BB * DECD];
__device__ float  g_ag[BB * 768];
__device__ float  g_gates[BB * GG];
__device__ __half g_mean16[BB * ENCD];
__device__ float  g_bag[768];
__device__ __half g_wag[512 * 768];
__device__ __half g_wg[768 * GG];
__device__ __half g_wtop[256 * GG];
__device__ __half g_wfc[512 * VPAD];
__device__ __half g_wenc[256 * 512];
__device__ __half g_wih0[256 * 512];
__device__ __half g_wic0[256 * 512];

__device__ __forceinline__ float sigmoidf(float x) { return 1.f / (1.f + expf(-x)); }

// ================= pipelined fp16 tensor-core GEMM =================
__device__ __forceinline__ uint32_t smem_u32(const void* p) {
    return (uint32_t)__cvta_generic_to_shared(p);
}
__device__ __forceinline__ void cp16(void* dst, const void* src) {
    asm volatile("cp.async.cg.shared.global [%0], [%1], 16;"
                 :: "r"(smem_u32(dst)), "l"(src));
}
__device__ __forceinline__ void cp_commit() { asm volatile("cp.async.commit_group;"); }
template<int N>
__device__ __forceinline__ void cp_wait() { asm volatile("cp.async.wait_group %0;" :: "n"(N)); }

__device__ __forceinline__ void ldm_x4(uint32_t* r, uint32_t addr) {
    asm volatile("ldmatrix.sync.aligned.m8n8.x4.shared.b16 {%0,%1,%2,%3}, [%4];"
                 : "=r"(r[0]), "=r"(r[1]), "=r"(r[2]), "=r"(r[3]) : "r"(addr));
}
__device__ __forceinline__ void ldm_x4_t(uint32_t* r, uint32_t addr) {
    asm volatile("ldmatrix.sync.aligned.m8n8.x4.trans.shared.b16 {%0,%1,%2,%3}, [%4];"
                 : "=r"(r[0]), "=r"(r[1]), "=r"(r[2]), "=r"(r[3]) : "r"(addr));
}
__device__ __forceinline__ void mma16816(float* c, const uint32_t* a, const uint32_t* b) {
    asm volatile("mma.sync.aligned.m16n8k16.row.col.f32.f16.f16.f32 "
                 "{%0,%1,%2,%3},{%4,%5,%6,%7},{%8,%9},{%0,%1,%2,%3};"
                 : "+f"(c[0]), "+f"(c[1]), "+f"(c[2]), "+f"(c[3])
                 : "r"(a[0]), "r"(a[1]), "r"(a[2]), "r"(a[3]), "r"(b[0]), "r"(b[1]));
}

// MODE: 0 fp32(+bias) | 1 att2gate (sigmoid n>=512) | 2 gates (+bias2+embW[cap])
//       3 fc t-major (tile skip, masked, transposed store) | 4 fp16 out (+bias)
// For MODE 3, 't' carries the chunk row offset (mbase).
template<int MODE>
__global__ __launch_bounds__(256)
void hgemm_k(const __half* __restrict__ A, int lda,
             const __half* __restrict__ W, int ldw,
             const float* __restrict__ bias, const float* __restrict__ bias2,
             float* __restrict__ Cf, __half* __restrict__ Ch, int ldc,
             int M, int N, int K,
             const int* __restrict__ caps, const int* __restrict__ lens,
             const float* __restrict__ embW, int t)
{
    extern __shared__ __half sm[];
    __half* As = sm;            // 3 stages * 8192 halves
    __half* Bs = sm + 24576;    // 3 stages * 8192 halves
    const int tid = threadIdx.x;
    const int warp = tid >> 5, lane = tid & 31;
    const int wm = (warp & 1) * 64, wn = (warp >> 1) * 32;
    const int m0 = blockIdx.y * 128 + (MODE == 3 ? t : 0);
    const int n0 = blockIdx.x * 128;

    if (MODE == 3) {
        int tt = m0 >> 8, bmin = m0 & 255;
        if (lens[bmin] <= tt) return;   // whole tile inactive (lens sorted desc)
    }

    float acc[4][4][4];
#pragma unroll
    for (int i = 0; i < 4; i++)
#pragma unroll
        for (int j = 0; j < 4; j++)
#pragma unroll
            for (int k = 0; k < 4; k++) acc[i][j][k] = 0.f;

    const int nk = K >> 6;

    // ---- async load helpers ----
#define LOAD_A(stage, kc)                                                        \
    {                                                                            \
        _Pragma("unroll")                                                        \
        for (int i = 0; i < 4; i++) {                                            \
            int idx = tid + i * 256;                                             \
            int r = idx >> 3, c = idx & 7;                                       \
            int gm = m0 + r; if (gm >= M) gm = M - 1;                            \
            cp16(As + (stage) * 8192 + r * 64 + (((c ^ r) & 7) << 3),            \
                 A + (size_t)gm * lda + (kc) + c * 8);                           \
        }                                                                        \
    }
#define LOAD_B(stage, kc)                                                        \
    {                                                                            \
        _Pragma("unroll")                                                        \
        for (int i = 0; i < 4; i++) {                                            \
            int idx = tid + i * 256;                                             \
            int r = idx >> 4, c = idx & 15;                                      \
            int sw = (c & 8) | ((c ^ r) & 7);                                    \
            cp16(Bs + (stage) * 8192 + r * 128 + (sw << 3),                      \
                 W + (size_t)((kc) + r) * ldw + n0 + c * 8);                     \
        }                                                                        \
    }

    // 3-stage prologue: stages 0 and 1 in flight
    LOAD_A(0, 0); LOAD_B(0, 0); cp_commit();
    if (nk > 1) { LOAD_A(1, 64); LOAD_B(1, 64); cp_commit(); }

    for (int k = 0; k < nk; k++) {
        int cur = k % 3;
        if (k + 2 < nk) {
            int nxt = (k + 2) % 3;
            LOAD_A(nxt, (k + 2) * 64);
            LOAD_B(nxt, (k + 2) * 64);
            cp_commit();
            cp_wait<2>();
        } else if (k + 1 < nk) {
            cp_wait<1>();
        } else {
            cp_wait<0>();
        }
        __syncthreads();

        const __half* Ab = As + cur * 8192;
        const __half* Bb = Bs + cur * 8192;
#pragma unroll
        for (int ks = 0; ks < 4; ks++) {
            uint32_t a[4][4], b[2][4];
#pragma unroll
            for (int mi = 0; mi < 4; mi++) {
                int m = wm + mi * 16 + (lane & 15);
                int kch = ks * 2 + (lane >> 4);
                ldm_x4(a[mi], smem_u32(Ab + m * 64 + (((kch ^ m) & 7) << 3)));
            }
#pragma unroll
            for (int ni = 0; ni < 2; ni++) {
                int kk = ks * 16 + (lane & 15);
                int nch = (wn >> 3) + ni * 2 + (lane >> 4);
                int sw = (nch & 8) | ((nch ^ kk) & 7);
                ldm_x4_t(b[ni], smem_u32(Bb + kk * 128 + (sw << 3)));
            }
#pragma unroll
            for (int mi = 0; mi < 4; mi++)
#pragma unroll
                for (int ni = 0; ni < 4; ni++)
                    mma16816(acc[mi][ni], a[mi], &b[ni >> 1][(ni & 1) * 2]);
        }
        __syncthreads();
    }
#undef LOAD_A
#undef LOAD_B

    // ---- epilogue ----
#pragma unroll
    for (int mi = 0; mi < 4; mi++) {
#pragma unroll
        for (int hh = 0; hh < 2; hh++) {
            int m = m0 + wm + mi * 16 + (lane >> 2) + hh * 8;
            if (m >= M) continue;
            int eidx = 0, active = 1, bo = 0, to = 0;
            if (MODE == 2) eidx = caps[m * TT + t];
            if (MODE == 3) {
                to = m >> 8; bo = m & 255;
                active = (lens[bo] > to);
            }
#pragma unroll
            for (int ni = 0; ni < 4; ni++) {
                int col = n0 + wn + ni * 8 + (lane & 3) * 2;
#pragma unroll
                for (int j = 0; j < 2; j++) {
                    int n = col + j;
                    float v = acc[mi][ni][hh * 2 + j];
                    if (bias) v += bias[n];
                    if (MODE == 0) {
                        Cf[(size_t)m * ldc + n] = v;
                    } else if (MODE == 1) {
                        if (n >= 512) v = sigmoidf(v);
                        Cf[(size_t)m * ldc + n] = v;
                    } else if (MODE == 2) {
                        v += bias2[n] + embW[(size_t)eidx * GG + n];
                        Cf[(size_t)m * ldc + n] = v;
                    } else if (MODE == 3) {
                        if (active && n < N)
                            Cf[((size_t)bo * TT + to) * ldc + n] = v;
                    } else {
                        Ch[(size_t)m * ldc + n] = __float2half(v);
                    }
                }
            }
        }
    }
}

// ================= small kernels =================
__global__ void cvt_k(const float* __restrict__ src, __half* __restrict__ dst,
                      int rows, int cols, int sld, int dld, int valid)
{
    int n = rows * cols;
    for (int i = blockIdx.x * blockDim.x + threadIdx.x; i < n; i += gridDim.x * blockDim.x) {
        int r = i / cols, c = i - r * cols;
        float v = (c < valid) ? src[(size_t)r * sld + c] : 0.f;
        dst[(size_t)r * dld + c] = __float2half(v);
    }
}

__global__ void mean_k(const float* __restrict__ enc)
{
    int b = blockIdx.x, e = threadIdx.x;
    const float* p = enc + (size_t)b * PP * ENCD + e;
    float s = 0.f;
#pragma unroll 8
    for (int pp = 0; pp < PP; pp++) s += p[(size_t)pp * ENCD];
    g_mean16[b * ENCD + e] = __float2half(s * (1.f / PP));
}

__global__ void bag_k(const float* __restrict__ b1, const float* __restrict__ b2)
{
    int i = threadIdx.x + blockIdx.x * blockDim.x;
    if (i < 512) g_bag[i] = b1[i];
    else if (i < 768) g_bag[i] = b2[i - 512];
}

__global__ void h0c_k()
{
    int b = blockIdx.x, d = threadIdx.x;
    g_xh[b * 768 + 256 + d] = __float2half(g_h[b * DECD + d]);
}

__global__ void lens_k(const int* __restrict__ lens, float* __restrict__ o)
{
    o[threadIdx.x] = (float)lens[threadIdx.x];
}

// fused attention: e -> softmax -> awe -> xg(fp16)
__global__ __launch_bounds__(256)
void attention_k(const float* __restrict__ wfull, const int* __restrict__ lens,
                 int t, float* __restrict__ alphas_out)
{
    __shared__ float att2s[DECD];
    __shared__ float wf[DECD];
    __shared__ float es[PP];
    __shared__ float red[32];
    int b = blockIdx.x, tid = threadIdx.x;
    att2s[tid]       = g_ag[b * 768 + tid];
    att2s[tid + 256] = g_ag[b * 768 + 256 + tid];
    wf[tid]       = wfull[tid];
    wf[tid + 256] = wfull[tid + 256];
    __syncthreads();

    int warp = tid >> 5, lane = tid & 31;
    const __half2* a1 = reinterpret_cast<const __half2*>(g_att1 + (size_t)b * PP * DECD);
    for (int p = warp; p < PP; p += 8) {
        const __half2* row = a1 + (size_t)p * (DECD / 2);
        float acc = 0.f;
#pragma unroll
        for (int i = 0; i < DECD / 64; i++) {
            int d2 = lane + 32 * i;
            float2 v = __half22float2(row[d2]);
            float x0 = v.x + att2s[2 * d2];
            float x1 = v.y + att2s[2 * d2 + 1];
            acc += fmaxf(x0, 0.f) * wf[2 * d2] + fmaxf(x1, 0.f) * wf[2 * d2 + 1];
        }
#pragma unroll
        for (int o = 16; o > 0; o >>= 1) acc += __shfl_xor_sync(0xffffffffu, acc, o);
        if (lane == 0) es[p] = acc;
    }
    __syncthreads();

    float e = es[tid];
    float m = e;
#pragma unroll
    for (int o = 16; o > 0; o >>= 1) m = fmaxf(m, __shfl_xor_sync(0xffffffffu, m, o));
    if (lane == 0) red[warp] = m;
    __syncthreads();
    if (tid == 0) {
        float mm = red[0];
        for (int w = 1; w < 8; w++) mm = fmaxf(mm, red[w]);
        red[16] = mm;
    }
    __syncthreads();
    float ex = expf(e - red[16]);
    float s = ex;
#pragma unroll
    for (int o = 16; o > 0; o >>= 1) s += __shfl_xor_sync(0xffffffffu, s, o);
    if (lane == 0) red[warp] = s;
    __syncthreads();
    if (tid == 0) {
        float ss = 0.f;
        for (int w = 0; w < 8; w++) ss += red[w];
        red[17] = ss;
    }
    __syncthreads();
    float alpha = ex / red[17];
    es[tid] = alpha;
    int active = lens[b] > t;
    alphas_out[((size_t)b * TT + t) * PP + tid] = active ? alpha : 0.f;
    __syncthreads();

    const __half* eb = g_encb + (size_t)b * PP * ENCD;
    float acc = 0.f;
#pragma unroll 8
    for (int p = 0; p < PP; p++) acc += es[p] * __half2float(eb[(size_t)p * ENCD + tid]);
    float gate = g_ag[b * 768 + 512 + tid];
    g_xh[b * 768 + tid] = __float2half(gate * acc);
}

// LSTM cell; h fp16 -> g_xh (recurrence) and g_hall t-major (fc batch)
__global__ void cell_k(const float* __restrict__ cold, float* __restrict__ cnew, int t)
{
    int b = blockIdx.x, d = threadIdx.x;
    const float* g = g_gates + (size_t)b * GG;
    float ig = sigmoidf(g[d]);
    float fg = sigmoidf(g[DECD + d]);
    float gg = tanhf(g[2 * DECD + d]);
    float og = sigmoidf(g[3 * DECD + d]);
    float c = fg * cold[b * DECD + d] + ig * gg;
    cnew[b * DECD + d] = c;
    __half hh = __float2half(og * tanhf(c));
    g_xh[b * 768 + 256 + d] = hh;
    g_hall[((size_t)t * BB + b) * DECD + d] = hh;
}

// ================= host orchestration =================
static inline int cgrid(int n) { int g = (n + 255) / 256; return g > 4096 ? 4096 : g; }

extern "C" void kernel_launch(void* const* d_in, const int* in_sizes, int n_in,
                              void* d_out, int out_size)
{
    const float* enc        = (const float*)d_in[0];
    const int*   caps       = (const int*)d_in[1];
    const int*   lens       = (const int*)d_in[2];
    const float* embedding  = (const float*)d_in[3];
    const float* enc_att_w  = (const float*)d_in[4];
    const float* enc_att_b  = (const float*)d_in[5];
    const float* dec_att_w  = (const float*)d_in[6];
    const float* dec_att_b  = (const float*)d_in[7];
    const float* full_att_w = (const float*)d_in[8];
    const float* lstm_wih   = (const float*)d_in[10];
    const float* lstm_whh   = (const float*)d_in[11];
    const float* lstm_bih   = (const float*)d_in[12];
    const float* lstm_bhh   = (const float*)d_in[13];
    const float* init_h_w   = (const float*)d_in[14];
    const float* init_h_b   = (const float*)d_in[15];
    const float* init_c_w   = (const float*)d_in[16];
    const float* init_c_b   = (const float*)d_in[17];
    const float* f_beta_w   = (const float*)d_in[18];
    const float* f_beta_b   = (const float*)d_in[19];
    const float* fc_w       = (const float*)d_in[20];
    const float* fc_b       = (const float*)d_in[21];

    float* out      = (float*)d_out;
    float* out_pred = out;
    float* out_lens = out + (size_t)BB * TT * VV;
    float* out_alph = out_lens + BB;

    cudaFuncSetAttribute(hgemm_k<0>, cudaFuncAttributeMaxDynamicSharedMemorySize, SMEMSZ);
    cudaFuncSetAttribute(hgemm_k<1>, cudaFuncAttributeMaxDynamicSharedMemorySize, SMEMSZ);
    cudaFuncSetAttribute(hgemm_k<2>, cudaFuncAttributeMaxDynamicSharedMemorySize, SMEMSZ);
    cudaFuncSetAttribute(hgemm_k<3>, cudaFuncAttributeMaxDynamicSharedMemorySize, SMEMSZ);
    cudaFuncSetAttribute(hgemm_k<4>, cudaFuncAttributeMaxDynamicSharedMemorySize, SMEMSZ);

    // second stream + events for fc overlap
    cudaStream_t s2;
    cudaStreamCreateWithFlags(&s2, cudaStreamNonBlocking);
    cudaEvent_t evA[TT / 8], evB[TT / 8];
    for (int i = 0; i < TT / 8; i++) {
        cudaEventCreateWithFlags(&evA[i], cudaEventDisableTiming);
        cudaEventCreateWithFlags(&evB[i], cudaEventDisableTiming);
    }

    // memset on s2: only fc (also on s2, in-order) needs it; alphas/lens fully
    // overwritten on stream 0. Keeps 494 MB zero-fill off the critical path.
    cudaMemsetAsync(d_out, 0, (size_t)out_size * sizeof(float), s2);

    __half *p_encb, *p_emb16, *p_xh, *p_hall, *p_mean16, *p_att1;
    __half *p_wag, *p_wg, *p_wtop, *p_wfc, *p_wenc, *p_wih0, *p_wic0;
    float *p_h, *p_c, *p_ag, *p_gates, *p_embW, *p_bag;
    cudaGetSymbolAddress((void**)&p_encb, g_encb);
    cudaGetSymbolAddress((void**)&p_emb16, g_emb16);
    cudaGetSymbolAddress((void**)&p_xh, g_xh);
    cudaGetSymbolAddress((void**)&p_hall, g_hall);
    cudaGetSymbolAddress((void**)&p_mean16, g_mean16);
    cudaGetSymbolAddress((void**)&p_att1, g_att1);
    cudaGetSymbolAddress((void**)&p_wag, g_wag);
    cudaGetSymbolAddress((void**)&p_wg, g_wg);
    cudaGetSymbolAddress((void**)&p_wtop, g_wtop);
    cudaGetSymbolAddress((void**)&p_wfc, g_wfc);
    cudaGetSymbolAddress((void**)&p_wenc, g_wenc);
    cudaGetSymbolAddress((void**)&p_wih0, g_wih0);
    cudaGetSymbolAddress((void**)&p_wic0, g_wic0);
    cudaGetSymbolAddress((void**)&p_h, g_h);
    cudaGetSymbolAddress((void**)&p_c, g_c);
    cudaGetSymbolAddress((void**)&p_ag, g_ag);
    cudaGetSymbolAddress((void**)&p_gates, g_gates);
    cudaGetSymbolAddress((void**)&p_embW, g_embW);
    cudaGetSymbolAddress((void**)&p_bag, g_bag);

    // ---- conversions (fp32 -> fp16) ----
    cvt_k<<<cgrid(BB * PP * ENCD), 256>>>(enc, p_encb, BB * PP, ENCD, ENCD, ENCD, ENCD);
    cvt_k<<<cgrid(VV * EE), 256>>>(embedding, p_emb16, VV, EE, EE, EE, EE);
    cvt_k<<<cgrid(512 * 512), 256>>>(dec_att_w, p_wag, 512, 512, 512, 768, 512);
    cvt_k<<<cgrid(512 * 256), 256>>>(f_beta_w, p_wag + 512, 512, 256, 256, 768, 256);
    cvt_k<<<cgrid(256 * GG), 256>>>(lstm_wih, p_wtop, 256, GG, GG, GG, GG);
    cvt_k<<<cgrid(256 * GG), 256>>>(lstm_wih + (size_t)EE * GG, p_wg, 256, GG, GG, GG, GG);
    cvt_k<<<cgrid(512 * GG), 256>>>(lstm_whh, p_wg + (size_t)256 * GG, 512, GG, GG, GG, GG);
    cvt_k<<<cgrid(512 * VPAD), 256>>>(fc_w, p_wfc, 512, VPAD, VV, VPAD, VV);
    cvt_k<<<cgrid(256 * 512), 256>>>(enc_att_w, p_wenc, 256, 512, 512, 512, 512);
    cvt_k<<<cgrid(256 * 512), 256>>>(init_h_w, p_wih0, 256, 512, 512, 512, 512);
    cvt_k<<<cgrid(256 * 512), 256>>>(init_c_w, p_wic0, 256, 512, 512, 512, 512);
    bag_k<<<3, 256>>>(dec_att_b, f_beta_b);
    mean_k<<<BB, 256>>>(enc);

    // ---- one-time TC GEMMs ----
    hgemm_k<0><<<dim3(DECD / 128, BB / 128), 256, SMEMSZ>>>(p_mean16, ENCD, p_wih0, DECD,
        init_h_b, nullptr, p_h, nullptr, DECD, BB, DECD, ENCD, nullptr, nullptr, nullptr, 0);
    hgemm_k<0><<<dim3(DECD / 128, BB / 128), 256, SMEMSZ>>>(p_mean16, ENCD, p_wic0, DECD,
        init_c_b, nullptr, p_c, nullptr, DECD, BB, DECD, ENCD, nullptr, nullptr, nullptr, 0);
    h0c_k<<<BB, DECD>>>();
    hgemm_k<4><<<dim3(DECD / 128, (BB * PP) / 128), 256, SMEMSZ>>>(p_encb, ENCD, p_wenc, DECD,
        enc_att_b, nullptr, nullptr, p_att1, DECD, BB * PP, DECD, ENCD, nullptr, nullptr, nullptr, 0);
    hgemm_k<0><<<dim3(GG / 128, (VV + 127) / 128), 256, SMEMSZ>>>(p_emb16, EE, p_wtop, GG,
        nullptr, nullptr, p_embW, nullptr, GG, VV, GG, EE, nullptr, nullptr, nullptr, 0);

    // ---- timestep loop; fc chunks forked to s2 every 8 steps ----
    for (int t = 0; t < TT; t++) {
        const float* ccur = p_c + (t & 1) * (BB * DECD);
        float*       cnext = p_c + ((t + 1) & 1) * (BB * DECD);

        hgemm_k<1><<<dim3(768 / 128, BB / 128), 256, SMEMSZ>>>(p_xh + 256, 768, p_wag, 768,
            p_bag, nullptr, p_ag, nullptr, 768, BB, 768, DECD, nullptr, nullptr, nullptr, 0);
        attention_k<<<BB, 256>>>(full_att_w, lens, t, out_alph);
        hgemm_k<2><<<dim3(GG / 128, BB / 128), 256, SMEMSZ>>>(p_xh, 768, p_wg, GG,
            lstm_bih, lstm_bhh, p_gates, nullptr, GG, BB, GG, 768, caps, nullptr, p_embW, t);
        cell_k<<<BB, DECD>>>(ccur, cnext, t);

        if ((t & 7) == 7) {
            int c = t >> 3;
            cudaEventRecord(evA[c], 0);
            cudaStreamWaitEvent(s2, evA[c], 0);
            hgemm_k<3><<<dim3(VPAD / 128, 16), 256, SMEMSZ, s2>>>(p_hall, DECD, p_wfc, VPAD,
                fc_b, nullptr, out_pred, nullptr, VV, BB * TT, VV, DECD,
                nullptr, lens, nullptr, c * 8 * BB);
            cudaEventRecord(evB[c], s2);
        }
    }

    // join fc chunks back to main stream
    for (int c = 0; c < TT / 8; c++) cudaStreamWaitEvent(0, evB[c], 0);

    lens_k<<<1, BB>>>(lens, out_lens);
}

// round 13
// speedup vs baseline: 1.3931x; 1.0024x over previous
#include <cuda_runtime.h>
#include <cuda_fp16.h>
#include <cstddef>
#include <cstdint>

#define BB   256
#define PP   256
#define ENCD 256
#define DECD 512
#define EE   256
#define VV   5000
#define TT   96
#define GG   2048
#define VPAD 5120

#define SMEMSZ 98304   // 3-stage: 3*(128*64 + 64*128) halves = 96 KB

// ---------------- device scratch ----------------
__device__ __half g_att1[(size_t)BB * PP * DECD];
__device__ __half g_encb[(size_t)BB * PP * ENCD];
__device__ float  g_embW[(size_t)VV * GG];
__device__ __half g_emb16[(size_t)VV * EE];
__device__ __half g_hall[(size_t)BB * TT * DECD];   // t-major: [(t*BB+b)*DECD+d]
__device__ __half g_xh[BB * (ENCD + DECD)];         // [xg | h], ld=768
__device__ float  g_h[BB * DECD];
__device__ float  g_c[2 * BB * DECD];
__device__ float  g_ag[BB * 768];
__device__ __half g_mean16[BB * ENCD];
__device__ float  g_bag[768];
__device__ __half g_wag[512 * 768];
__device__ __half g_wg[768 * GG];
__device__ __half g_wtop[256 * GG];
__device__ __half g_wfc[512 * VPAD];
__device__ __half g_wenc[256 * 512];
__device__ __half g_wih0[256 * 512];
__device__ __half g_wic0[256 * 512];

__device__ __forceinline__ float sigmoidf(float x) { return 1.f / (1.f + expf(-x)); }

// ================= pipelined fp16 tensor-core GEMM primitives =================
__device__ __forceinline__ uint32_t smem_u32(const void* p) {
    return (uint32_t)__cvta_generic_to_shared(p);
}
__device__ __forceinline__ void cp16(void* dst, const void* src) {
    asm volatile("cp.async.cg.shared.global [%0], [%1], 16;"
                 :: "r"(smem_u32(dst)), "l"(src));
}
__device__ __forceinline__ void cp_commit() { asm volatile("cp.async.commit_group;"); }
template<int N>
__device__ __forceinline__ void cp_wait() { asm volatile("cp.async.wait_group %0;" :: "n"(N)); }

__device__ __forceinline__ void ldm_x4(uint32_t* r, uint32_t addr) {
    asm volatile("ldmatrix.sync.aligned.m8n8.x4.shared.b16 {%0,%1,%2,%3}, [%4];"
                 : "=r"(r[0]), "=r"(r[1]), "=r"(r[2]), "=r"(r[3]) : "r"(addr));
}
__device__ __forceinline__ void ldm_x4_t(uint32_t* r, uint32_t addr) {
    asm volatile("ldmatrix.sync.aligned.m8n8.x4.trans.shared.b16 {%0,%1,%2,%3}, [%4];"
                 : "=r"(r[0]), "=r"(r[1]), "=r"(r[2]), "=r"(r[3]) : "r"(addr));
}
__device__ __forceinline__ void mma16816(float* c, const uint32_t* a, const uint32_t* b) {
    asm volatile("mma.sync.aligned.m16n8k16.row.col.f32.f16.f16.f32 "
                 "{%0,%1,%2,%3},{%4,%5,%6,%7},{%8,%9},{%0,%1,%2,%3};"
                 : "+f"(c[0]), "+f"(c[1]), "+f"(c[2]), "+f"(c[3])
                 : "r"(a[0]), "r"(a[1]), "r"(a[2]), "r"(a[3]), "r"(b[0]), "r"(b[1]));
}

// MODE: 0 fp32(+bias) | 1 att2gate (sigmoid n>=512)
//       3 fc t-major (tile skip, masked, transposed store) | 4 fp16 out (+bias)
// For MODE 3, 't' carries the chunk row offset (mbase).
template<int MODE>
__global__ __launch_bounds__(256)
void hgemm_k(const __half* __restrict__ A, int lda,
             const __half* __restrict__ W, int ldw,
             const float* __restrict__ bias,
             float* __restrict__ Cf, __half* __restrict__ Ch, int ldc,
             int M, int N, int K,
             const int* __restrict__ lens, int t)
{
    extern __shared__ __half sm[];
    __half* As = sm;            // 3 stages * 8192 halves
    __half* Bs = sm + 24576;    // 3 stages * 8192 halves
    const int tid = threadIdx.x;
    const int warp = tid >> 5, lane = tid & 31;
    const int wm = (warp & 1) * 64, wn = (warp >> 1) * 32;
    const int m0 = blockIdx.y * 128 + (MODE == 3 ? t : 0);
    const int n0 = blockIdx.x * 128;

    if (MODE == 3) {
        int tt = m0 >> 8, bmin = m0 & 255;
        if (lens[bmin] <= tt) return;   // whole tile inactive (lens sorted desc)
    }

    float acc[4][4][4];
#pragma unroll
    for (int i = 0; i < 4; i++)
#pragma unroll
        for (int j = 0; j < 4; j++)
#pragma unroll
            for (int k = 0; k < 4; k++) acc[i][j][k] = 0.f;

    const int nk = K >> 6;

#define LOAD_A(stage, kc)                                                        \
    {                                                                            \
        _Pragma("unroll")                                                        \
        for (int i = 0; i < 4; i++) {                                            \
            int idx = tid + i * 256;                                             \
            int r = idx >> 3, c = idx & 7;                                       \
            int gm = m0 + r; if (gm >= M) gm = M - 1;                            \
            cp16(As + (stage) * 8192 + r * 64 + (((c ^ r) & 7) << 3),            \
                 A + (size_t)gm * lda + (kc) + c * 8);                           \
        }                                                                        \
    }
#define LOAD_B(stage, kc)                                                        \
    {                                                                            \
        _Pragma("unroll")                                                        \
        for (int i = 0; i < 4; i++) {                                            \
            int idx = tid + i * 256;                                             \
            int r = idx >> 4, c = idx & 15;                                      \
            int sw = (c & 8) | ((c ^ r) & 7);                                    \
            cp16(Bs + (stage) * 8192 + r * 128 + (sw << 3),                      \
                 W + (size_t)((kc) + r) * ldw + n0 + c * 8);                     \
        }                                                                        \
    }

    LOAD_A(0, 0); LOAD_B(0, 0); cp_commit();
    if (nk > 1) { LOAD_A(1, 64); LOAD_B(1, 64); cp_commit(); }

    for (int k = 0; k < nk; k++) {
        int cur = k % 3;
        if (k + 2 < nk) {
            int nxt = (k + 2) % 3;
            LOAD_A(nxt, (k + 2) * 64);
            LOAD_B(nxt, (k + 2) * 64);
            cp_commit();
            cp_wait<2>();
        } else if (k + 1 < nk) {
            cp_wait<1>();
        } else {
            cp_wait<0>();
        }
        __syncthreads();

        const __half* Ab = As + cur * 8192;
        const __half* Bb = Bs + cur * 8192;
#pragma unroll
        for (int ks = 0; ks < 4; ks++) {
            uint32_t a[4][4], b[2][4];
#pragma unroll
            for (int mi = 0; mi < 4; mi++) {
                int m = wm + mi * 16 + (lane & 15);
                int kch = ks * 2 + (lane >> 4);
                ldm_x4(a[mi], smem_u32(Ab + m * 64 + (((kch ^ m) & 7) << 3)));
            }
#pragma unroll
            for (int ni = 0; ni < 2; ni++) {
                int kk = ks * 16 + (lane & 15);
                int nch = (wn >> 3) + ni * 2 + (lane >> 4);
                int sw = (nch & 8) | ((nch ^ kk) & 7);
                ldm_x4_t(b[ni], smem_u32(Bb + kk * 128 + (sw << 3)));
            }
#pragma unroll
            for (int mi = 0; mi < 4; mi++)
#pragma unroll
                for (int ni = 0; ni < 4; ni++)
                    mma16816(acc[mi][ni], a[mi], &b[ni >> 1][(ni & 1) * 2]);
        }
        __syncthreads();
    }
#undef LOAD_A
#undef LOAD_B

#pragma unroll
    for (int mi = 0; mi < 4; mi++) {
#pragma unroll
        for (int hh = 0; hh < 2; hh++) {
            int m = m0 + wm + mi * 16 + (lane >> 2) + hh * 8;
            if (m >= M) continue;
            int active = 1, bo = 0, to = 0;
            if (MODE == 3) {
                to = m >> 8; bo = m & 255;
                active = (lens[bo] > to);
            }
#pragma unroll
            for (int ni = 0; ni < 4; ni++) {
                int col = n0 + wn + ni * 8 + (lane & 3) * 2;
#pragma unroll
                for (int j = 0; j < 2; j++) {
                    int n = col + j;
                    float v = acc[mi][ni][hh * 2 + j];
                    if (bias) v += bias[n];
                    if (MODE == 0) {
                        Cf[(size_t)m * ldc + n] = v;
                    } else if (MODE == 1) {
                        if (n >= 512) v = sigmoidf(v);
                        Cf[(size_t)m * ldc + n] = v;
                    } else if (MODE == 3) {
                        if (active && n < N)
                            Cf[((size_t)bo * TT + to) * ldc + n] = v;
                    } else {
                        Ch[(size_t)m * ldc + n] = __float2half(v);
                    }
                }
            }
        }
    }
}

// ============ fused gates GEMM + LSTM cell ============
// Grid (16, 2). Block computes a 128-row x 128-col tile of gates, where the 128
// columns are 4 strips of 32: global col = strip*512 + d0 + (col%32), strip = gate.
// The block thus holds i/f/g/o for (128 rows x 32 d) and finishes the LSTM cell
// in-block via an smem exchange — no g_gates buffer, no separate cell launch.
__global__ __launch_bounds__(256)
void gates_cell_k(const float* __restrict__ bih, const float* __restrict__ bhh,
                  const int* __restrict__ caps,
                  const float* __restrict__ cold, float* __restrict__ cnew, int t)
{
    extern __shared__ __half sm[];
    __half* As = sm;
    __half* Bs = sm + 24576;
    const int tid = threadIdx.x;
    const int warp = tid >> 5, lane = tid & 31;
    const int wm = (warp & 1) * 64, wn = (warp >> 1) * 32;
    const int m0 = blockIdx.y * 128;
    const int d0 = blockIdx.x * 32;

    float acc[4][4][4];
#pragma unroll
    for (int i = 0; i < 4; i++)
#pragma unroll
        for (int j = 0; j < 4; j++)
#pragma unroll
            for (int k = 0; k < 4; k++) acc[i][j][k] = 0.f;

    const int nk = 768 >> 6;   // 12

#define GLOAD_A(stage, kc)                                                       \
    {                                                                            \
        _Pragma("unroll")                                                        \
        for (int i = 0; i < 4; i++) {                                            \
            int idx = tid + i * 256;                                             \
            int r = idx >> 3, c = idx & 7;                                       \
            cp16(As + (stage) * 8192 + r * 64 + (((c ^ r) & 7) << 3),            \
                 g_xh + (size_t)(m0 + r) * 768 + (kc) + c * 8);                  \
        }                                                                        \
    }
// chunk c (0..15): local cols c*8..c*8+7 -> global col (c>>2)*512 + d0 + (c&3)*8
#define GLOAD_B(stage, kc)                                                       \
    {                                                                            \
        _Pragma("unroll")                                                        \
        for (int i = 0; i < 4; i++) {                                            \
            int idx = tid + i * 256;                                             \
            int r = idx >> 4, c = idx & 15;                                      \
            int sw = (c & 8) | ((c ^ r) & 7);                                    \
            int gcol = ((c >> 2) << 9) + d0 + ((c & 3) << 3);                    \
            cp16(Bs + (stage) * 8192 + r * 128 + (sw << 3),                      \
                 g_wg + (size_t)((kc) + r) * GG + gcol);                         \
        }                                                                        \
    }

    GLOAD_A(0, 0); GLOAD_B(0, 0); cp_commit();
    GLOAD_A(1, 64); GLOAD_B(1, 64); cp_commit();

    for (int k = 0; k < nk; k++) {
        int cur = k % 3;
        if (k + 2 < nk) {
            int nxt = (k + 2) % 3;
            GLOAD_A(nxt, (k + 2) * 64);
            GLOAD_B(nxt, (k + 2) * 64);
            cp_commit();
            cp_wait<2>();
        } else if (k + 1 < nk) {
            cp_wait<1>();
        } else {
            cp_wait<0>();
        }
        __syncthreads();

        const __half* Ab = As + cur * 8192;
        const __half* Bb = Bs + cur * 8192;
#pragma unroll
        for (int ks = 0; ks < 4; ks++) {
            uint32_t a[4][4], b[2][4];
#pragma unroll
            for (int mi = 0; mi < 4; mi++) {
                int m = wm + mi * 16 + (lane & 15);
                int kch = ks * 2 + (lane >> 4);
                ldm_x4(a[mi], smem_u32(Ab + m * 64 + (((kch ^ m) & 7) << 3)));
            }
#pragma unroll
            for (int ni = 0; ni < 2; ni++) {
                int kk = ks * 16 + (lane & 15);
                int nch = (wn >> 3) + ni * 2 + (lane >> 4);
                int sw = (nch & 8) | ((nch ^ kk) & 7);
                ldm_x4_t(b[ni], smem_u32(Bb + kk * 128 + (sw << 3)));
            }
#pragma unroll
            for (int mi = 0; mi < 4; mi++)
#pragma unroll
                for (int ni = 0; ni < 4; ni++)
                    mma16816(acc[mi][ni], a[mi], &b[ni >> 1][(ni & 1) * 2]);
        }
        __syncthreads();
    }
#undef GLOAD_A
#undef GLOAD_B

    // ---- stage pre-activations (+bias+embW) to smem, then cell ----
    float* smf = reinterpret_cast<float*>(sm);   // 128 x 132 floats = 67.6 KB
#pragma unroll
    for (int mi = 0; mi < 4; mi++) {
#pragma unroll
        for (int hh = 0; hh < 2; hh++) {
            int ml = wm + mi * 16 + (lane >> 2) + hh * 8;
            int eidx = caps[(m0 + ml) * TT + t];
#pragma unroll
            for (int ni = 0; ni < 4; ni++) {
#pragma unroll
                for (int j = 0; j < 2; j++) {
                    int nl = wn + ni * 8 + (lane & 3) * 2 + j;
                    int gcol = ((nl >> 5) << 9) + d0 + (nl & 31);
                    smf[ml * 132 + nl] = acc[mi][ni][hh * 2 + j]
                        + bih[gcol] + bhh[gcol] + g_embW[(size_t)eidx * GG + gcol];
                }
            }
        }
    }
    __syncthreads();

    for (int e = tid; e < 128 * 32; e += 256) {
        int ml = e >> 5, dl = e & 31;
        float iv = smf[ml * 132 + dl];
        float fv = smf[ml * 132 + 32 + dl];
        float gv = smf[ml * 132 + 64 + dl];
        float ov = smf[ml * 132 + 96 + dl];
        int b = m0 + ml, d = d0 + dl;
        float c = sigmoidf(fv) * cold[b * DECD + d] + sigmoidf(iv) * tanhf(gv);
        cnew[b * DECD + d] = c;
        __half hh = __float2half(sigmoidf(ov) * tanhf(c));
        g_xh[b * 768 + 256 + d] = hh;
        g_hall[((size_t)t * BB + b) * DECD + d] = hh;
    }
}

// ================= small kernels =================
__global__ void cvt_k(const float* __restrict__ src, __half* __restrict__ dst,
                      int rows, int cols, int sld, int dld, int valid)
{
    int n = rows * cols;
    for (int i = blockIdx.x * blockDim.x + threadIdx.x; i < n; i += gridDim.x * blockDim.x) {
        int r = i / cols, c = i - r * cols;
        float v = (c < valid) ? src[(size_t)r * sld + c] : 0.f;
        dst[(size_t)r * dld + c] = __float2half(v);
    }
}

__global__ void mean_k(const float* __restrict__ enc)
{
    int b = blockIdx.x, e = threadIdx.x;
    const float* p = enc + (size_t)b * PP * ENCD + e;
    float s = 0.f;
#pragma unroll 8
    for (int pp = 0; pp < PP; pp++) s += p[(size_t)pp * ENCD];
    g_mean16[b * ENCD + e] = __float2half(s * (1.f / PP));
}

__global__ void bag_k(const float* __restrict__ b1, const float* __restrict__ b2)
{
    int i = threadIdx.x + blockIdx.x * blockDim.x;
    if (i < 512) g_bag[i] = b1[i];
    else if (i < 768) g_bag[i] = b2[i - 512];
}

__global__ void h0c_k()
{
    int b = blockIdx.x, d = threadIdx.x;
    g_xh[b * 768 + 256 + d] = __float2half(g_h[b * DECD + d]);
}

__global__ void lens_k(const int* __restrict__ lens, float* __restrict__ o)
{
    o[threadIdx.x] = (float)lens[threadIdx.x];
}

// fused attention: e -> softmax -> awe -> xg(fp16)
__global__ __launch_bounds__(256)
void attention_k(const float* __restrict__ wfull, const int* __restrict__ lens,
                 int t, float* __restrict__ alphas_out)
{
    __shared__ float att2s[DECD];
    __shared__ float wf[DECD];
    __shared__ float es[PP];
    __shared__ float red[32];
    int b = blockIdx.x, tid = threadIdx.x;
    att2s[tid]       = g_ag[b * 768 + tid];
    att2s[tid + 256] = g_ag[b * 768 + 256 + tid];
    wf[tid]       = wfull[tid];
    wf[tid + 256] = wfull[tid + 256];
    __syncthreads();

    int warp = tid >> 5, lane = tid & 31;
    const __half2* a1 = reinterpret_cast<const __half2*>(g_att1 + (size_t)b * PP * DECD);
    for (int p = warp; p < PP; p += 8) {
        const __half2* row = a1 + (size_t)p * (DECD / 2);
        float acc = 0.f;
#pragma unroll
        for (int i = 0; i < DECD / 64; i++) {
            int d2 = lane + 32 * i;
            float2 v = __half22float2(row[d2]);
            float x0 = v.x + att2s[2 * d2];
            float x1 = v.y + att2s[2 * d2 + 1];
            acc += fmaxf(x0, 0.f) * wf[2 * d2] + fmaxf(x1, 0.f) * wf[2 * d2 + 1];
        }
#pragma unroll
        for (int o = 16; o > 0; o >>= 1) acc += __shfl_xor_sync(0xffffffffu, acc, o);
        if (lane == 0) es[p] = acc;
    }
    __syncthreads();

    float e = es[tid];
    float m = e;
#pragma unroll
    for (int o = 16; o > 0; o >>= 1) m = fmaxf(m, __shfl_xor_sync(0xffffffffu, m, o));
    if (lane == 0) red[warp] = m;
    __syncthreads();
    if (tid == 0) {
        float mm = red[0];
        for (int w = 1; w < 8; w++) mm = fmaxf(mm, red[w]);
        red[16] = mm;
    }
    __syncthreads();
    float ex = expf(e - red[16]);
    float s = ex;
#pragma unroll
    for (int o = 16; o > 0; o >>= 1) s += __shfl_xor_sync(0xffffffffu, s, o);
    if (lane == 0) red[warp] = s;
    __syncthreads();
    if (tid == 0) {
        float ss = 0.f;
        for (int w = 0; w < 8; w++) ss += red[w];
        red[17] = ss;
    }
    __syncthreads();
    float alpha = ex / red[17];
    es[tid] = alpha;
    int active = lens[b] > t;
    alphas_out[((size_t)b * TT + t) * PP + tid] = active ? alpha : 0.f;
    __syncthreads();

    const __half* eb = g_encb + (size_t)b * PP * ENCD;
    float acc = 0.f;
#pragma unroll 8
    for (int p = 0; p < PP; p++) acc += es[p] * __half2float(eb[(size_t)p * ENCD + tid]);
    float gate = g_ag[b * 768 + 512 + tid];
    g_xh[b * 768 + tid] = __float2half(gate * acc);
}

// ================= host orchestration =================
static inline int cgrid(int n) { int g = (n + 255) / 256; return g > 4096 ? 4096 : g; }

extern "C" void kernel_launch(void* const* d_in, const int* in_sizes, int n_in,
                              void* d_out, int out_size)
{
    const float* enc        = (const float*)d_in[0];
    const int*   caps       = (const int*)d_in[1];
    const int*   lens       = (const int*)d_in[2];
    const float* embedding  = (const float*)d_in[3];
    const float* enc_att_w  = (const float*)d_in[4];
    const float* enc_att_b  = (const float*)d_in[5];
    const float* dec_att_w  = (const float*)d_in[6];
    const float* dec_att_b  = (const float*)d_in[7];
    const float* full_att_w = (const float*)d_in[8];
    const float* lstm_wih   = (const float*)d_in[10];
    const float* lstm_whh   = (const float*)d_in[11];
    const float* lstm_bih   = (const float*)d_in[12];
    const float* lstm_bhh   = (const float*)d_in[13];
    const float* init_h_w   = (const float*)d_in[14];
    const float* init_h_b   = (const float*)d_in[15];
    const float* init_c_w   = (const float*)d_in[16];
    const float* init_c_b   = (const float*)d_in[17];
    const float* f_beta_w   = (const float*)d_in[18];
    const float* f_beta_b   = (const float*)d_in[19];
    const float* fc_w       = (const float*)d_in[20];
    const float* fc_b       = (const float*)d_in[21];

    float* out      = (float*)d_out;
    float* out_pred = out;
    float* out_lens = out + (size_t)BB * TT * VV;
    float* out_alph = out_lens + BB;

    cudaFuncSetAttribute(hgemm_k<0>, cudaFuncAttributeMaxDynamicSharedMemorySize, SMEMSZ);
    cudaFuncSetAttribute(hgemm_k<1>, cudaFuncAttributeMaxDynamicSharedMemorySize, SMEMSZ);
    cudaFuncSetAttribute(hgemm_k<3>, cudaFuncAttributeMaxDynamicSharedMemorySize, SMEMSZ);
    cudaFuncSetAttribute(hgemm_k<4>, cudaFuncAttributeMaxDynamicSharedMemorySize, SMEMSZ);
    cudaFuncSetAttribute(gates_cell_k, cudaFuncAttributeMaxDynamicSharedMemorySize, SMEMSZ);

    cudaStream_t s2;
    cudaStreamCreateWithFlags(&s2, cudaStreamNonBlocking);
    cudaEvent_t evA[TT / 8], evB[TT / 8], evP, evF;
    for (int i = 0; i < TT / 8; i++) {
        cudaEventCreateWithFlags(&evA[i], cudaEventDisableTiming);
        cudaEventCreateWithFlags(&evB[i], cudaEventDisableTiming);
    }
    cudaEventCreateWithFlags(&evP, cudaEventDisableTiming);
    cudaEventCreateWithFlags(&evF, cudaEventDisableTiming);

    __half *p_encb, *p_emb16, *p_xh, *p_hall, *p_mean16, *p_att1;
    __half *p_wag, *p_wg, *p_wtop, *p_wfc, *p_wenc, *p_wih0, *p_wic0;
    float *p_h, *p_c, *p_ag, *p_embW, *p_bag;
    cudaGetSymbolAddress((void**)&p_encb, g_encb);
    cudaGetSymbolAddress((void**)&p_emb16, g_emb16);
    cudaGetSymbolAddress((void**)&p_xh, g_xh);
    cudaGetSymbolAddress((void**)&p_hall, g_hall);
    cudaGetSymbolAddress((void**)&p_mean16, g_mean16);
    cudaGetSymbolAddress((void**)&p_att1, g_att1);
    cudaGetSymbolAddress((void**)&p_wag, g_wag);
    cudaGetSymbolAddress((void**)&p_wg, g_wg);
    cudaGetSymbolAddress((void**)&p_wtop, g_wtop);
    cudaGetSymbolAddress((void**)&p_wfc, g_wfc);
    cudaGetSymbolAddress((void**)&p_wenc, g_wenc);
    cudaGetSymbolAddress((void**)&p_wih0, g_wih0);
    cudaGetSymbolAddress((void**)&p_wic0, g_wic0);
    cudaGetSymbolAddress((void**)&p_h, g_h);
    cudaGetSymbolAddress((void**)&p_c, g_c);
    cudaGetSymbolAddress((void**)&p_ag, g_ag);
    cudaGetSymbolAddress((void**)&p_embW, g_embW);
    cudaGetSymbolAddress((void**)&p_bag, g_bag);

    // ---- capture-legal fork of s2 from the origin stream ----
    cudaEventRecord(evF, 0);
    cudaStreamWaitEvent(s2, evF, 0);

    // ---- s2: embW precompute chain, then prediction-region memset ----
    cvt_k<<<cgrid(VV * EE), 256, 0, s2>>>(embedding, p_emb16, VV, EE, EE, EE, EE);
    cvt_k<<<cgrid(256 * GG), 256, 0, s2>>>(lstm_wih, p_wtop, 256, GG, GG, GG, GG);
    hgemm_k<0><<<dim3(GG / 128, (VV + 127) / 128), 256, SMEMSZ, s2>>>(p_emb16, EE, p_wtop, GG,
        nullptr, p_embW, nullptr, GG, VV, GG, EE, nullptr, 0);
    cudaEventRecord(evP, s2);
    // zero ONLY the predictions region (alphas/lens fully overwritten on stream 0);
    // in-order on s2 => completes before the first fc chunk.
    cudaMemsetAsync(out_pred, 0, (size_t)BB * TT * VV * sizeof(float), s2);

    // ---- stream 0: remaining conversions ----
    cvt_k<<<cgrid(BB * PP * ENCD), 256>>>(enc, p_encb, BB * PP, ENCD, ENCD, ENCD, ENCD);
    cvt_k<<<cgrid(512 * 512), 256>>>(dec_att_w, p_wag, 512, 512, 512, 768, 512);
    cvt_k<<<cgrid(512 * 256), 256>>>(f_beta_w, p_wag + 512, 512, 256, 256, 768, 256);
    cvt_k<<<cgrid(256 * GG), 256>>>(lstm_wih + (size_t)EE * GG, p_wg, 256, GG, GG, GG, GG);
    cvt_k<<<cgrid(512 * GG), 256>>>(lstm_whh, p_wg + (size_t)256 * GG, 512, GG, GG, GG, GG);
    cvt_k<<<cgrid(512 * VPAD), 256>>>(fc_w, p_wfc, 512, VPAD, VV, VPAD, VV);
    cvt_k<<<cgrid(256 * 512), 256>>>(enc_att_w, p_wenc, 256, 512, 512, 512, 512);
    cvt_k<<<cgrid(256 * 512), 256>>>(init_h_w, p_wih0, 256, 512, 512, 512, 512);
    cvt_k<<<cgrid(256 * 512), 256>>>(init_c_w, p_wic0, 256, 512, 512, 512, 512);
    bag_k<<<3, 256>>>(dec_att_b, f_beta_b);
    mean_k<<<BB, 256>>>(enc);

    // ---- one-time TC GEMMs (stream 0, overlapped with s2's embW GEMM) ----
    hgemm_k<0><<<dim3(DECD / 128, BB / 128), 256, SMEMSZ>>>(p_mean16, ENCD, p_wih0, DECD,
        init_h_b, p_h, nullptr, DECD, BB, DECD, ENCD, nullptr, 0);
    hgemm_k<0><<<dim3(DECD / 128, BB / 128), 256, SMEMSZ>>>(p_mean16, ENCD, p_wic0, DECD,
        init_c_b, p_c, nullptr, DECD, BB, DECD, ENCD, nullptr, 0);
    h0c_k<<<BB, DECD>>>();
    hgemm_k<4><<<dim3(DECD / 128, (BB * PP) / 128), 256, SMEMSZ>>>(p_encb, ENCD, p_wenc, DECD,
        enc_att_b, nullptr, p_att1, DECD, BB * PP, DECD, ENCD, nullptr, 0);
    lens_k<<<1, BB>>>(lens, out_lens);

    // join s2 precompute (embW needed by gates_cell at t=0)
    cudaStreamWaitEvent(0, evP, 0);

    // ---- timestep loop: 3 launches/step; fc chunks forked to s2 every 8 steps ----
    for (int t = 0; t < TT; t++) {
        const float* ccur = p_c + (t & 1) * (BB * DECD);
        float*       cnext = p_c + ((t + 1) & 1) * (BB * DECD);

        hgemm_k<1><<<dim3(768 / 128, BB / 128), 256, SMEMSZ>>>(p_xh + 256, 768, p_wag, 768,
            p_bag, p_ag, nullptr, 768, BB, 768, DECD, nullptr, 0);
        attention_k<<<BB, 256>>>(full_att_w, lens, t, out_alph);
        gates_cell_k<<<dim3(16, 2), 256, SMEMSZ>>>(lstm_bih, lstm_bhh, caps, ccur, cnext, t);

        if ((t & 7) == 7) {
            int c = t >> 3;
            cudaEventRecord(evA[c], 0);
            cudaStreamWaitEvent(s2, evA[c], 0);
            hgemm_k<3><<<dim3(VPAD / 128, 16), 256, SMEMSZ, s2>>>(p_hall, DECD, p_wfc, VPAD,
                fc_b, out_pred, nullptr, VV, BB * TT, VV, DECD, lens, c * 8 * BB);
            cudaEventRecord(evB[c], s2);
        }
    }

    for (int c = 0; c < TT / 8; c++) cudaStreamWaitEvent(0, evB[c], 0);
}

// round 14
// speedup vs baseline: 1.6135x; 1.1582x over previous
#include <cuda_runtime.h>
#include <cuda_fp16.h>
#include <cstddef>
#include <cstdint>

#define BB   256
#define PP   256
#define ENCD 256
#define DECD 512
#define EE   256
#define VV   5000
#define TT   96
#define GG   2048
#define VPAD 5120

#define SMEMSZ 98304    // MF=4: 3*(128*64 + 64*128) halves = 96 KB
#define SMEMSZ2 73728   // MF=2: 3*(64*64 + 64*128) halves = 72 KB

// ---------------- device scratch ----------------
__device__ __half g_att1[(size_t)BB * PP * DECD];
__device__ __half g_encb[(size_t)BB * PP * ENCD];
__device__ float  g_embW[(size_t)VV * GG];
__device__ __half g_emb16[(size_t)VV * EE];
__device__ __half g_hall[(size_t)BB * TT * DECD];   // t-major
__device__ __half g_xh[BB * (ENCD + DECD)];         // [xg | h], ld=768
__device__ float  g_h[BB * DECD];
__device__ float  g_c[2 * BB * DECD];
__device__ float  g_ag[BB * 768];
__device__ __half g_mean16[BB * ENCD];
__device__ float  g_bag[768];
__device__ __half g_wag[512 * 768];
__device__ __half g_wg[768 * GG];
__device__ __half g_wtop[256 * GG];
__device__ __half g_wfc[512 * VPAD];
__device__ __half g_wenc[256 * 512];
__device__ __half g_wih0[256 * 512];
__device__ __half g_wic0[256 * 512];

__device__ __forceinline__ float sigmoidf(float x) { return 1.f / (1.f + expf(-x)); }

__device__ __forceinline__ uint32_t smem_u32(const void* p) {
    return (uint32_t)__cvta_generic_to_shared(p);
}
__device__ __forceinline__ void cp16(void* dst, const void* src) {
    asm volatile("cp.async.cg.shared.global [%0], [%1], 16;"
                 :: "r"(smem_u32(dst)), "l"(src));
}
__device__ __forceinline__ void cp_commit() { asm volatile("cp.async.commit_group;"); }
template<int N>
__device__ __forceinline__ void cp_wait() { asm volatile("cp.async.wait_group %0;" :: "n"(N)); }

__device__ __forceinline__ void ldm_x4(uint32_t* r, uint32_t addr) {
    asm volatile("ldmatrix.sync.aligned.m8n8.x4.shared.b16 {%0,%1,%2,%3}, [%4];"
                 : "=r"(r[0]), "=r"(r[1]), "=r"(r[2]), "=r"(r[3]) : "r"(addr));
}
__device__ __forceinline__ void ldm_x4_t(uint32_t* r, uint32_t addr) {
    asm volatile("ldmatrix.sync.aligned.m8n8.x4.trans.shared.b16 {%0,%1,%2,%3}, [%4];"
                 : "=r"(r[0]), "=r"(r[1]), "=r"(r[2]), "=r"(r[3]) : "r"(addr));
}
__device__ __forceinline__ void mma16816(float* c, const uint32_t* a, const uint32_t* b) {
    asm volatile("mma.sync.aligned.m16n8k16.row.col.f32.f16.f16.f32 "
                 "{%0,%1,%2,%3},{%4,%5,%6,%7},{%8,%9},{%0,%1,%2,%3};"
                 : "+f"(c[0]), "+f"(c[1]), "+f"(c[2]), "+f"(c[3])
                 : "r"(a[0]), "r"(a[1]), "r"(a[2]), "r"(a[3]), "r"(b[0]), "r"(b[1]));
}

// ================= MF=4 (128-row) GEMM: precompute + fc =================
// MODE: 0 fp32(+bias) | 3 fc t-major (tile skip, masked) | 4 fp16 out (+bias)
template<int MODE>
__global__ __launch_bounds__(256)
void hgemm_k(const __half* __restrict__ A, int lda,
             const __half* __restrict__ W, int ldw,
             const float* __restrict__ bias,
             float* __restrict__ Cf, __half* __restrict__ Ch, int ldc,
             int M, int N, int K,
             const int* __restrict__ lens, int t)
{
    extern __shared__ __half sm[];
    __half* As = sm;            // 3 stages * 8192 halves
    __half* Bs = sm + 24576;
    const int tid = threadIdx.x;
    const int warp = tid >> 5, lane = tid & 31;
    const int wm = (warp & 1) * 64, wn = (warp >> 1) * 32;
    const int m0 = blockIdx.y * 128 + (MODE == 3 ? t : 0);
    const int n0 = blockIdx.x * 128;

    if (MODE == 3) {
        int tt = m0 >> 8, bmin = m0 & 255;
        if (lens[bmin] <= tt) return;
    }

    float acc[4][4][4];
#pragma unroll
    for (int i = 0; i < 4; i++)
#pragma unroll
        for (int j = 0; j < 4; j++)
#pragma unroll
            for (int k = 0; k < 4; k++) acc[i][j][k] = 0.f;

    const int nk = K >> 6;

#define LOAD_A(stage, kc)                                                        \
    {                                                                            \
        _Pragma("unroll")                                                        \
        for (int i = 0; i < 4; i++) {                                            \
            int idx = tid + i * 256;                                             \
            int r = idx >> 3, c = idx & 7;                                       \
            int gm = m0 + r; if (gm >= M) gm = M - 1;                            \
            cp16(As + (stage) * 8192 + r * 64 + (((c ^ r) & 7) << 3),            \
                 A + (size_t)gm * lda + (kc) + c * 8);                           \
        }                                                                        \
    }
#define LOAD_B(stage, kc)                                                        \
    {                                                                            \
        _Pragma("unroll")                                                        \
        for (int i = 0; i < 4; i++) {                                            \
            int idx = tid + i * 256;                                             \
            int r = idx >> 4, c = idx & 15;                                      \
            int sw = (c & 8) | ((c ^ r) & 7);                                    \
            cp16(Bs + (stage) * 8192 + r * 128 + (sw << 3),                      \
                 W + (size_t)((kc) + r) * ldw + n0 + c * 8);                     \
        }                                                                        \
    }

    LOAD_A(0, 0); LOAD_B(0, 0); cp_commit();
    if (nk > 1) { LOAD_A(1, 64); LOAD_B(1, 64); cp_commit(); }

    for (int k = 0; k < nk; k++) {
        int cur = k % 3;
        if (k + 2 < nk) {
            int nxt = (k + 2) % 3;
            LOAD_A(nxt, (k + 2) * 64);
            LOAD_B(nxt, (k + 2) * 64);
            cp_commit();
            cp_wait<2>();
        } else if (k + 1 < nk) {
            cp_wait<1>();
        } else {
            cp_wait<0>();
        }
        __syncthreads();
        const __half* Ab = As + cur * 8192;
        const __half* Bb = Bs + cur * 8192;
#pragma unroll
        for (int ks = 0; ks < 4; ks++) {
            uint32_t a[4][4], b[2][4];
#pragma unroll
            for (int mi = 0; mi < 4; mi++) {
                int m = wm + mi * 16 + (lane & 15);
                int kch = ks * 2 + (lane >> 4);
                ldm_x4(a[mi], smem_u32(Ab + m * 64 + (((kch ^ m) & 7) << 3)));
            }
#pragma unroll
            for (int ni = 0; ni < 2; ni++) {
                int kk = ks * 16 + (lane & 15);
                int nch = (wn >> 3) + ni * 2 + (lane >> 4);
                int sw = (nch & 8) | ((nch ^ kk) & 7);
                ldm_x4_t(b[ni], smem_u32(Bb + kk * 128 + (sw << 3)));
            }
#pragma unroll
            for (int mi = 0; mi < 4; mi++)
#pragma unroll
                for (int ni = 0; ni < 4; ni++)
                    mma16816(acc[mi][ni], a[mi], &b[ni >> 1][(ni & 1) * 2]);
        }
        __syncthreads();
    }
#undef LOAD_A
#undef LOAD_B

#pragma unroll
    for (int mi = 0; mi < 4; mi++) {
#pragma unroll
        for (int hh = 0; hh < 2; hh++) {
            int m = m0 + wm + mi * 16 + (lane >> 2) + hh * 8;
            if (m >= M) continue;
            int active = 1, bo = 0, to = 0;
            if (MODE == 3) {
                to = m >> 8; bo = m & 255;
                active = (lens[bo] > to);
            }
#pragma unroll
            for (int ni = 0; ni < 4; ni++) {
                int col = n0 + wn + ni * 8 + (lane & 3) * 2;
#pragma unroll
                for (int j = 0; j < 2; j++) {
                    int n = col + j;
                    float v = acc[mi][ni][hh * 2 + j];
                    if (bias) v += bias[n];
                    if (MODE == 0) {
                        Cf[(size_t)m * ldc + n] = v;
                    } else if (MODE == 3) {
                        if (active && n < N)
                            Cf[((size_t)bo * TT + to) * ldc + n] = v;
                    } else {
                        Ch[(size_t)m * ldc + n] = __float2half(v);
                    }
                }
            }
        }
    }
}

// ================= MF=2 (64-row) AG GEMM: [att2|gate] = h @ wag + bag =================
// Grid (6, 4): m0 = by*64, n0 = bx*128. K=512.
__global__ __launch_bounds__(256)
void ag_k()
{
    extern __shared__ __half sm[];
    __half* As = sm;             // 3 stages * 4096 halves
    __half* Bs = sm + 12288;     // 3 stages * 8192 halves
    const int tid = threadIdx.x;
    const int warp = tid >> 5, lane = tid & 31;
    const int wm = (warp & 1) * 32, wn = (warp >> 1) * 32;
    const int m0 = blockIdx.y * 64;
    const int n0 = blockIdx.x * 128;

    float acc[2][4][4];
#pragma unroll
    for (int i = 0; i < 2; i++)
#pragma unroll
        for (int j = 0; j < 4; j++)
#pragma unroll
            for (int k = 0; k < 4; k++) acc[i][j][k] = 0.f;

    const int nk = 8;   // K=512

#define ALOAD_A(stage, kc)                                                       \
    {                                                                            \
        _Pragma("unroll")                                                        \
        for (int i = 0; i < 2; i++) {                                            \
            int idx = tid + i * 256;                                             \
            int r = idx >> 3, c = idx & 7;                                       \
            cp16(As + (stage) * 4096 + r * 64 + (((c ^ r) & 7) << 3),            \
                 g_xh + (size_t)(m0 + r) * 768 + 256 + (kc) + c * 8);            \
        }                                                                        \
    }
#define ALOAD_B(stage, kc)                                                       \
    {                                                                            \
        _Pragma("unroll")                                                        \
        for (int i = 0; i < 4; i++) {                                            \
            int idx = tid + i * 256;                                             \
            int r = idx >> 4, c = idx & 15;                                      \
            int sw = (c & 8) | ((c ^ r) & 7);                                    \
            cp16(Bs + (stage) * 8192 + r * 128 + (sw << 3),                      \
                 g_wag + (size_t)((kc) + r) * 768 + n0 + c * 8);                 \
        }                                                                        \
    }

    ALOAD_A(0, 0); ALOAD_B(0, 0); cp_commit();
    ALOAD_A(1, 64); ALOAD_B(1, 64); cp_commit();

    for (int k = 0; k < nk; k++) {
        int cur = k % 3;
        if (k + 2 < nk) {
            int nxt = (k + 2) % 3;
            ALOAD_A(nxt, (k + 2) * 64);
            ALOAD_B(nxt, (k + 2) * 64);
            cp_commit();
            cp_wait<2>();
        } else if (k + 1 < nk) {
            cp_wait<1>();
        } else {
            cp_wait<0>();
        }
        __syncthreads();
        const __half* Ab = As + cur * 4096;
        const __half* Bb = Bs + cur * 8192;
#pragma unroll
        for (int ks = 0; ks < 4; ks++) {
            uint32_t a[2][4], b[2][4];
#pragma unroll
            for (int mi = 0; mi < 2; mi++) {
                int m = wm + mi * 16 + (lane & 15);
                int kch = ks * 2 + (lane >> 4);
                ldm_x4(a[mi], smem_u32(Ab + m * 64 + (((kch ^ m) & 7) << 3)));
            }
#pragma unroll
            for (int ni = 0; ni < 2; ni++) {
                int kk = ks * 16 + (lane & 15);
                int nch = (wn >> 3) + ni * 2 + (lane >> 4);
                int sw = (nch & 8) | ((nch ^ kk) & 7);
                ldm_x4_t(b[ni], smem_u32(Bb + kk * 128 + (sw << 3)));
            }
#pragma unroll
            for (int mi = 0; mi < 2; mi++)
#pragma unroll
                for (int ni = 0; ni < 4; ni++)
                    mma16816(acc[mi][ni], a[mi], &b[ni >> 1][(ni & 1) * 2]);
        }
        __syncthreads();
    }
#undef ALOAD_A
#undef ALOAD_B

#pragma unroll
    for (int mi = 0; mi < 2; mi++) {
#pragma unroll
        for (int hh = 0; hh < 2; hh++) {
            int m = m0 + wm + mi * 16 + (lane >> 2) + hh * 8;
#pragma unroll
            for (int ni = 0; ni < 4; ni++) {
                int col = n0 + wn + ni * 8 + (lane & 3) * 2;
#pragma unroll
                for (int j = 0; j < 2; j++) {
                    int n = col + j;
                    float v = acc[mi][ni][hh * 2 + j] + g_bag[n];
                    if (n >= 512) v = sigmoidf(v);
                    g_ag[m * 768 + n] = v;
                }
            }
        }
    }
}

// ================= MF=2 (64-row) fused gates GEMM + LSTM cell =================
// Grid (16, 4): m0 = by*64, d0 = bx*32. Cols = 4 gate strips of 32.
__global__ __launch_bounds__(256)
void gates_cell_k(const float* __restrict__ bih, const float* __restrict__ bhh,
                  const int* __restrict__ caps,
                  const float* __restrict__ cold, float* __restrict__ cnew, int t)
{
    extern __shared__ __half sm[];
    __half* As = sm;             // 3 stages * 4096 halves
    __half* Bs = sm + 12288;
    const int tid = threadIdx.x;
    const int warp = tid >> 5, lane = tid & 31;
    const int wm = (warp & 1) * 32, wn = (warp >> 1) * 32;
    const int m0 = blockIdx.y * 64;
    const int d0 = blockIdx.x * 32;

    float acc[2][4][4];
#pragma unroll
    for (int i = 0; i < 2; i++)
#pragma unroll
        for (int j = 0; j < 4; j++)
#pragma unroll
            for (int k = 0; k < 4; k++) acc[i][j][k] = 0.f;

    const int nk = 12;  // K=768

#define GLOAD_A(stage, kc)                                                       \
    {                                                                            \
        _Pragma("unroll")                                                        \
        for (int i = 0; i < 2; i++) {                                            \
            int idx = tid + i * 256;                                             \
            int r = idx >> 3, c = idx & 7;                                       \
            cp16(As + (stage) * 4096 + r * 64 + (((c ^ r) & 7) << 3),            \
                 g_xh + (size_t)(m0 + r) * 768 + (kc) + c * 8);                  \
        }                                                                        \
    }
#define GLOAD_B(stage, kc)                                                       \
    {                                                                            \
        _Pragma("unroll")                                                        \
        for (int i = 0; i < 4; i++) {                                            \
            int idx = tid + i * 256;                                             \
            int r = idx >> 4, c = idx & 15;                                      \
            int sw = (c & 8) | ((c ^ r) & 7);                                    \
            int gcol = ((c >> 2) << 9) + d0 + ((c & 3) << 3);                    \
            cp16(Bs + (stage) * 8192 + r * 128 + (sw << 3),                      \
                 g_wg + (size_t)((kc) + r) * GG + gcol);                         \
        }                                                                        \
    }

    GLOAD_A(0, 0); GLOAD_B(0, 0); cp_commit();
    GLOAD_A(1, 64); GLOAD_B(1, 64); cp_commit();

    for (int k = 0; k < nk; k++) {
        int cur = k % 3;
        if (k + 2 < nk) {
            int nxt = (k + 2) % 3;
            GLOAD_A(nxt, (k + 2) * 64);
            GLOAD_B(nxt, (k + 2) * 64);
            cp_commit();
            cp_wait<2>();
        } else if (k + 1 < nk) {
            cp_wait<1>();
        } else {
            cp_wait<0>();
        }
        __syncthreads();
        const __half* Ab = As + cur * 4096;
        const __half* Bb = Bs + cur * 8192;
#pragma unroll
        for (int ks = 0; ks < 4; ks++) {
            uint32_t a[2][4], b[2][4];
#pragma unroll
            for (int mi = 0; mi < 2; mi++) {
                int m = wm + mi * 16 + (lane & 15);
                int kch = ks * 2 + (lane >> 4);
                ldm_x4(a[mi], smem_u32(Ab + m * 64 + (((kch ^ m) & 7) << 3)));
            }
#pragma unroll
            for (int ni = 0; ni < 2; ni++) {
                int kk = ks * 16 + (lane & 15);
                int nch = (wn >> 3) + ni * 2 + (lane >> 4);
                int sw = (nch & 8) | ((nch ^ kk) & 7);
                ldm_x4_t(b[ni], smem_u32(Bb + kk * 128 + (sw << 3)));
            }
#pragma unroll
            for (int mi = 0; mi < 2; mi++)
#pragma unroll
                for (int ni = 0; ni < 4; ni++)
                    mma16816(acc[mi][ni], a[mi], &b[ni >> 1][(ni & 1) * 2]);
        }
        __syncthreads();
    }
#undef GLOAD_A
#undef GLOAD_B

    // stage pre-activations (+biases+embW) to smem, then cell (64 x 128 floats)
    float* smf = reinterpret_cast<float*>(sm);   // 64 x 132 floats = 33.8 KB
#pragma unroll
    for (int mi = 0; mi < 2; mi++) {
#pragma unroll
        for (int hh = 0; hh < 2; hh++) {
            int ml = wm + mi * 16 + (lane >> 2) + hh * 8;
            int eidx = caps[(m0 + ml) * TT + t];
#pragma unroll
            for (int ni = 0; ni < 4; ni++) {
#pragma unroll
                for (int j = 0; j < 2; j++) {
                    int nl = wn + ni * 8 + (lane & 3) * 2 + j;
                    int gcol = ((nl >> 5) << 9) + d0 + (nl & 31);
                    smf[ml * 132 + nl] = acc[mi][ni][hh * 2 + j]
                        + bih[gcol] + bhh[gcol] + g_embW[(size_t)eidx * GG + gcol];
                }
            }
        }
    }
    __syncthreads();

    for (int e = tid; e < 64 * 32; e += 256) {
        int ml = e >> 5, dl = e & 31;
        float iv = smf[ml * 132 + dl];
        float fv = smf[ml * 132 + 32 + dl];
        float gv = smf[ml * 132 + 64 + dl];
        float ov = smf[ml * 132 + 96 + dl];
        int b = m0 + ml, d = d0 + dl;
        float c = sigmoidf(fv) * cold[b * DECD + d] + sigmoidf(iv) * tanhf(gv);
        cnew[b * DECD + d] = c;
        __half hh = __float2half(sigmoidf(ov) * tanhf(c));
        g_xh[b * 768 + 256 + d] = hh;
        g_hall[((size_t)t * BB + b) * DECD + d] = hh;
    }
}

// ================= small kernels =================
__global__ void cvt_k(const float* __restrict__ src, __half* __restrict__ dst,
                      int rows, int cols, int sld, int dld, int valid)
{
    int n = rows * cols;
    for (int i = blockIdx.x * blockDim.x + threadIdx.x; i < n; i += gridDim.x * blockDim.x) {
        int r = i / cols, c = i - r * cols;
        float v = (c < valid) ? src[(size_t)r * sld + c] : 0.f;
        dst[(size_t)r * dld + c] = __float2half(v);
    }
}

__global__ void mean_k(const float* __restrict__ enc)
{
    int b = blockIdx.x, e = threadIdx.x;
    const float* p = enc + (size_t)b * PP * ENCD + e;
    float s = 0.f;
#pragma unroll 8
    for (int pp = 0; pp < PP; pp++) s += p[(size_t)pp * ENCD];
    g_mean16[b * ENCD + e] = __float2half(s * (1.f / PP));
}

__global__ void bag_k(const float* __restrict__ b1, const float* __restrict__ b2)
{
    int i = threadIdx.x + blockIdx.x * blockDim.x;
    if (i < 512) g_bag[i] = b1[i];
    else if (i < 768) g_bag[i] = b2[i - 512];
}

__global__ void h0c_k()
{
    int b = blockIdx.x, d = threadIdx.x;
    g_xh[b * 768 + 256 + d] = __float2half(g_h[b * DECD + d]);
}

__global__ void lens_k(const int* __restrict__ lens, float* __restrict__ o)
{
    o[threadIdx.x] = (float)lens[threadIdx.x];
}

// fused attention: e -> softmax -> awe -> xg(fp16)
__global__ __launch_bounds__(256)
void attention_k(const float* __restrict__ wfull, const int* __restrict__ lens,
                 int t, float* __restrict__ alphas_out)
{
    __shared__ float att2s[DECD];
    __shared__ float wf[DECD];
    __shared__ float es[PP];
    __shared__ float red[32];
    int b = blockIdx.x, tid = threadIdx.x;
    att2s[tid]       = g_ag[b * 768 + tid];
    att2s[tid + 256] = g_ag[b * 768 + 256 + tid];
    wf[tid]       = wfull[tid];
    wf[tid + 256] = wfull[tid + 256];
    __syncthreads();

    int warp = tid >> 5, lane = tid & 31;
    const __half2* a1 = reinterpret_cast<const __half2*>(g_att1 + (size_t)b * PP * DECD);
    for (int p = warp; p < PP; p += 8) {
        const __half2* row = a1 + (size_t)p * (DECD / 2);
        float acc = 0.f;
#pragma unroll
        for (int i = 0; i < DECD / 64; i++) {
            int d2 = lane + 32 * i;
            float2 v = __half22float2(row[d2]);
            float x0 = v.x + att2s[2 * d2];
            float x1 = v.y + att2s[2 * d2 + 1];
            acc += fmaxf(x0, 0.f) * wf[2 * d2] + fmaxf(x1, 0.f) * wf[2 * d2 + 1];
        }
#pragma unroll
        for (int o = 16; o > 0; o >>= 1) acc += __shfl_xor_sync(0xffffffffu, acc, o);
        if (lane == 0) es[p] = acc;
    }
    __syncthreads();

    float e = es[tid];
    float m = e;
#pragma unroll
    for (int o = 16; o > 0; o >>= 1) m = fmaxf(m, __shfl_xor_sync(0xffffffffu, m, o));
    if (lane == 0) red[warp] = m;
    __syncthreads();
    if (tid == 0) {
        float mm = red[0];
        for (int w = 1; w < 8; w++) mm = fmaxf(mm, red[w]);
        red[16] = mm;
    }
    __syncthreads();
    float ex = expf(e - red[16]);
    float s = ex;
#pragma unroll
    for (int o = 16; o > 0; o >>= 1) s += __shfl_xor_sync(0xffffffffu, s, o);
    if (lane == 0) red[warp] = s;
    __syncthreads();
    if (tid == 0) {
        float ss = 0.f;
        for (int w = 0; w < 8; w++) ss += red[w];
        red[17] = ss;
    }
    __syncthreads();
    float alpha = ex / red[17];
    es[tid] = alpha;
    int active = lens[b] > t;
    alphas_out[((size_t)b * TT + t) * PP + tid] = active ? alpha : 0.f;
    __syncthreads();

    const __half* eb = g_encb + (size_t)b * PP * ENCD;
    float acc = 0.f;
#pragma unroll 8
    for (int p = 0; p < PP; p++) acc += es[p] * __half2float(eb[(size_t)p * ENCD + tid]);
    float gate = g_ag[b * 768 + 512 + tid];
    g_xh[b * 768 + tid] = __float2half(gate * acc);
}

// ================= host orchestration =================
static inline int cgrid(int n) { int g = (n + 255) / 256; return g > 4096 ? 4096 : g; }

extern "C" void kernel_launch(void* const* d_in, const int* in_sizes, int n_in,
                              void* d_out, int out_size)
{
    const float* enc        = (const float*)d_in[0];
    const int*   caps       = (const int*)d_in[1];
    const int*   lens       = (const int*)d_in[2];
    const float* embedding  = (const float*)d_in[3];
    const float* enc_att_w  = (const float*)d_in[4];
    const float* enc_att_b  = (const float*)d_in[5];
    const float* dec_att_w  = (const float*)d_in[6];
    const float* dec_att_b  = (const float*)d_in[7];
    const float* full_att_w = (const float*)d_in[8];
    const float* lstm_wih   = (const float*)d_in[10];
    const float* lstm_whh   = (const float*)d_in[11];
    const float* lstm_bih   = (const float*)d_in[12];
    const float* lstm_bhh   = (const float*)d_in[13];
    const float* init_h_w   = (const float*)d_in[14];
    const float* init_h_b   = (const float*)d_in[15];
    const float* init_c_w   = (const float*)d_in[16];
    const float* init_c_b   = (const float*)d_in[17];
    const float* f_beta_w   = (const float*)d_in[18];
    const float* f_beta_b   = (const float*)d_in[19];
    const float* fc_w       = (const float*)d_in[20];
    const float* fc_b       = (const float*)d_in[21];

    float* out      = (float*)d_out;
    float* out_pred = out;
    float* out_lens = out + (size_t)BB * TT * VV;
    float* out_alph = out_lens + BB;

    cudaFuncSetAttribute(hgemm_k<0>, cudaFuncAttributeMaxDynamicSharedMemorySize, SMEMSZ);
    cudaFuncSetAttribute(hgemm_k<3>, cudaFuncAttributeMaxDynamicSharedMemorySize, SMEMSZ);
    cudaFuncSetAttribute(hgemm_k<4>, cudaFuncAttributeMaxDynamicSharedMemorySize, SMEMSZ);
    cudaFuncSetAttribute(ag_k, cudaFuncAttributeMaxDynamicSharedMemorySize, SMEMSZ2);
    cudaFuncSetAttribute(gates_cell_k, cudaFuncAttributeMaxDynamicSharedMemorySize, SMEMSZ2);

    cudaStream_t s2;
    cudaStreamCreateWithFlags(&s2, cudaStreamNonBlocking);
    cudaEvent_t evA[TT / 8], evB[TT / 8], evP, evF;
    for (int i = 0; i < TT / 8; i++) {
        cudaEventCreateWithFlags(&evA[i], cudaEventDisableTiming);
        cudaEventCreateWithFlags(&evB[i], cudaEventDisableTiming);
    }
    cudaEventCreateWithFlags(&evP, cudaEventDisableTiming);
    cudaEventCreateWithFlags(&evF, cudaEventDisableTiming);

    __half *p_encb, *p_emb16, *p_xh, *p_hall, *p_mean16, *p_att1;
    __half *p_wag, *p_wg, *p_wtop, *p_wfc, *p_wenc, *p_wih0, *p_wic0;
    float *p_h, *p_c, *p_ag, *p_embW, *p_bag;
    cudaGetSymbolAddress((void**)&p_encb, g_encb);
    cudaGetSymbolAddress((void**)&p_emb16, g_emb16);
    cudaGetSymbolAddress((void**)&p_xh, g_xh);
    cudaGetSymbolAddress((void**)&p_hall, g_hall);
    cudaGetSymbolAddress((void**)&p_mean16, g_mean16);
    cudaGetSymbolAddress((void**)&p_att1, g_att1);
    cudaGetSymbolAddress((void**)&p_wag, g_wag);
    cudaGetSymbolAddress((void**)&p_wg, g_wg);
    cudaGetSymbolAddress((void**)&p_wtop, g_wtop);
    cudaGetSymbolAddress((void**)&p_wfc, g_wfc);
    cudaGetSymbolAddress((void**)&p_wenc, g_wenc);
    cudaGetSymbolAddress((void**)&p_wih0, g_wih0);
    cudaGetSymbolAddress((void**)&p_wic0, g_wic0);
    cudaGetSymbolAddress((void**)&p_h, g_h);
    cudaGetSymbolAddress((void**)&p_c, g_c);
    cudaGetSymbolAddress((void**)&p_ag, g_ag);
    cudaGetSymbolAddress((void**)&p_embW, g_embW);
    cudaGetSymbolAddress((void**)&p_bag, g_bag);

    // capture-legal fork of s2
    cudaEventRecord(evF, 0);
    cudaStreamWaitEvent(s2, evF, 0);

    // s2: embW precompute chain, then prediction-region memset
    cvt_k<<<cgrid(VV * EE), 256, 0, s2>>>(embedding, p_emb16, VV, EE, EE, EE, EE);
    cvt_k<<<cgrid(256 * GG), 256, 0, s2>>>(lstm_wih, p_wtop, 256, GG, GG, GG, GG);
    hgemm_k<0><<<dim3(GG / 128, (VV + 127) / 128), 256, SMEMSZ, s2>>>(p_emb16, EE, p_wtop, GG,
        nullptr, p_embW, nullptr, GG, VV, GG, EE, nullptr, 0);
    cudaEventRecord(evP, s2);
    cudaMemsetAsync(out_pred, 0, (size_t)BB * TT * VV * sizeof(float), s2);

    // stream 0: remaining conversions
    cvt_k<<<cgrid(BB * PP * ENCD), 256>>>(enc, p_encb, BB * PP, ENCD, ENCD, ENCD, ENCD);
    cvt_k<<<cgrid(512 * 512), 256>>>(dec_att_w, p_wag, 512, 512, 512, 768, 512);
    cvt_k<<<cgrid(512 * 256), 256>>>(f_beta_w, p_wag + 512, 512, 256, 256, 768, 256);
    cvt_k<<<cgrid(256 * GG), 256>>>(lstm_wih + (size_t)EE * GG, p_wg, 256, GG, GG, GG, GG);
    cvt_k<<<cgrid(512 * GG), 256>>>(lstm_whh, p_wg + (size_t)256 * GG, 512, GG, GG, GG, GG);
    cvt_k<<<cgrid(512 * VPAD), 256>>>(fc_w, p_wfc, 512, VPAD, VV, VPAD, VV);
    cvt_k<<<cgrid(256 * 512), 256>>>(enc_att_w, p_wenc, 256, 512, 512, 512, 512);
    cvt_k<<<cgrid(256 * 512), 256>>>(init_h_w, p_wih0, 256, 512, 512, 512, 512);
    cvt_k<<<cgrid(256 * 512), 256>>>(init_c_w, p_wic0, 256, 512, 512, 512, 512);
    bag_k<<<3, 256>>>(dec_att_b, f_beta_b);
    mean_k<<<BB, 256>>>(enc);

    // one-time TC GEMMs
    hgemm_k<0><<<dim3(DECD / 128, BB / 128), 256, SMEMSZ>>>(p_mean16, ENCD, p_wih0, DECD,
        init_h_b, p_h, nullptr, DECD, BB, DECD, ENCD, nullptr, 0);
    hgemm_k<0><<<dim3(DECD / 128, BB / 128), 256, SMEMSZ>>>(p_mean16, ENCD, p_wic0, DECD,
        init_c_b, p_c, nullptr, DECD, BB, DECD, ENCD, nullptr, 0);
    h0c_k<<<BB, DECD>>>();
    hgemm_k<4><<<dim3(DECD / 128, (BB * PP) / 128), 256, SMEMSZ>>>(p_encb, ENCD, p_wenc, DECD,
        enc_att_b, nullptr, p_att1, DECD, BB * PP, DECD, ENCD, nullptr, 0);
    lens_k<<<1, BB>>>(lens, out_lens);

    // join s2 precompute (embW needed by gates_cell at t=0)
    cudaStreamWaitEvent(0, evP, 0);

    // timestep loop: 3 launches/step with 64-row loop GEMM tiles
    for (int t = 0; t < TT; t++) {
        const float* ccur = p_c + (t & 1) * (BB * DECD);
        float*       cnext = p_c + ((t + 1) & 1) * (BB * DECD);

        ag_k<<<dim3(6, 4), 256, SMEMSZ2>>>();
        attention_k<<<BB, 256>>>(full_att_w, lens, t, out_alph);
        gates_cell_k<<<dim3(16, 4), 256, SMEMSZ2>>>(lstm_bih, lstm_bhh, caps, ccur, cnext, t);

        if ((t & 7) == 7) {
            int c = t >> 3;
            cudaEventRecord(evA[c], 0);
            cudaStreamWaitEvent(s2, evA[c], 0);
            hgemm_k<3><<<dim3(VPAD / 128, 16), 256, SMEMSZ, s2>>>(p_hall, DECD, p_wfc, VPAD,
                fc_b, out_pred, nullptr, VV, BB * TT, VV, DECD, lens, c * 8 * BB);
            cudaEventRecord(evB[c], s2);
        }
    }

    for (int c = 0; c < TT / 8; c++) cudaStreamWaitEvent(0, evB[c], 0);
}

// round 15
// speedup vs baseline: 1.6422x; 1.0178x over previous
#include <cuda_runtime.h>
#include <cuda_fp16.h>
#include <cstddef>
#include <cstdint>

#define BB   256
#define PP   256
#define ENCD 256
#define DECD 512
#define EE   256
#define VV   5000
#define TT   96
#define GG   2048
#define VPAD 5120

#define SMEMSZ 98304    // MF=4: 3*(128*64 + 64*128) halves = 96 KB
#define SMEMSZ2 73728   // MF=2: 3*(64*64 + 64*128) halves = 72 KB

// ---------------- device scratch ----------------
__device__ __half g_att1[(size_t)BB * PP * DECD];
__device__ __half g_encb[(size_t)BB * PP * ENCD];
__device__ float  g_embW[(size_t)VV * GG];
__device__ __half g_emb16[(size_t)VV * EE];
__device__ __half g_hall[(size_t)BB * TT * DECD];   // t-major
__device__ __half g_xh[BB * (ENCD + DECD)];         // [xg | h], ld=768
__device__ float  g_h[BB * DECD];
__device__ float  g_c[2 * BB * DECD];
__device__ float  g_ag[BB * 768];
__device__ float  g_gates[BB * GG];                 // h@Whh partial (gate-strip cols)
__device__ __half g_mean16[BB * ENCD];
__device__ float  g_bag[768];
__device__ __half g_wag[512 * 768];
__device__ __half g_wg[768 * GG];                   // rows 0..255: wih_bot; 256..767: whh
__device__ __half g_wtop[256 * GG];
__device__ __half g_wfc[512 * VPAD];
__device__ __half g_wenc[256 * 512];
__device__ __half g_wih0[256 * 512];
__device__ __half g_wic0[256 * 512];

__device__ __forceinline__ float sigmoidf(float x) { return 1.f / (1.f + expf(-x)); }

__device__ __forceinline__ uint32_t smem_u32(const void* p) {
    return (uint32_t)__cvta_generic_to_shared(p);
}
__device__ __forceinline__ void cp16(void* dst, const void* src) {
    asm volatile("cp.async.cg.shared.global [%0], [%1], 16;"
                 :: "r"(smem_u32(dst)), "l"(src));
}
__device__ __forceinline__ void cp_commit() { asm volatile("cp.async.commit_group;"); }
template<int N>
__device__ __forceinline__ void cp_wait() { asm volatile("cp.async.wait_group %0;" :: "n"(N)); }

__device__ __forceinline__ void ldm_x4(uint32_t* r, uint32_t addr) {
    asm volatile("ldmatrix.sync.aligned.m8n8.x4.shared.b16 {%0,%1,%2,%3}, [%4];"
                 : "=r"(r[0]), "=r"(r[1]), "=r"(r[2]), "=r"(r[3]) : "r"(addr));
}
__device__ __forceinline__ void ldm_x4_t(uint32_t* r, uint32_t addr) {
    asm volatile("ldmatrix.sync.aligned.m8n8.x4.trans.shared.b16 {%0,%1,%2,%3}, [%4];"
                 : "=r"(r[0]), "=r"(r[1]), "=r"(r[2]), "=r"(r[3]) : "r"(addr));
}
__device__ __forceinline__ void mma16816(float* c, const uint32_t* a, const uint32_t* b) {
    asm volatile("mma.sync.aligned.m16n8k16.row.col.f32.f16.f16.f32 "
                 "{%0,%1,%2,%3},{%4,%5,%6,%7},{%8,%9},{%0,%1,%2,%3};"
                 : "+f"(c[0]), "+f"(c[1]), "+f"(c[2]), "+f"(c[3])
                 : "r"(a[0]), "r"(a[1]), "r"(a[2]), "r"(a[3]), "r"(b[0]), "r"(b[1]));
}

// ================= MF=4 (128-row) GEMM: precompute + fc =================
// MODE: 0 fp32(+bias) | 3 fc t-major (tile skip, masked) | 4 fp16 out (+bias)
template<int MODE>
__global__ __launch_bounds__(256)
void hgemm_k(const __half* __restrict__ A, int lda,
             const __half* __restrict__ W, int ldw,
             const float* __restrict__ bias,
             float* __restrict__ Cf, __half* __restrict__ Ch, int ldc,
             int M, int N, int K,
             const int* __restrict__ lens, int t)
{
    extern __shared__ __half sm[];
    __half* As = sm;
    __half* Bs = sm + 24576;
    const int tid = threadIdx.x;
    const int warp = tid >> 5, lane = tid & 31;
    const int wm = (warp & 1) * 64, wn = (warp >> 1) * 32;
    const int m0 = blockIdx.y * 128 + (MODE == 3 ? t : 0);
    const int n0 = blockIdx.x * 128;

    if (MODE == 3) {
        int tt = m0 >> 8, bmin = m0 & 255;
        if (lens[bmin] <= tt) return;
    }

    float acc[4][4][4];
#pragma unroll
    for (int i = 0; i < 4; i++)
#pragma unroll
        for (int j = 0; j < 4; j++)
#pragma unroll
            for (int k = 0; k < 4; k++) acc[i][j][k] = 0.f;

    const int nk = K >> 6;

#define LOAD_A(stage, kc)                                                        \
    {                                                                            \
        _Pragma("unroll")                                                        \
        for (int i = 0; i < 4; i++) {                                            \
            int idx = tid + i * 256;                                             \
            int r = idx >> 3, c = idx & 7;                                       \
            int gm = m0 + r; if (gm >= M) gm = M - 1;                            \
            cp16(As + (stage) * 8192 + r * 64 + (((c ^ r) & 7) << 3),            \
                 A + (size_t)gm * lda + (kc) + c * 8);                           \
        }                                                                        \
    }
#define LOAD_B(stage, kc)                                                        \
    {                                                                            \
        _Pragma("unroll")                                                        \
        for (int i = 0; i < 4; i++) {                                            \
            int idx = tid + i * 256;                                             \
            int r = idx >> 4, c = idx & 15;                                      \
            int sw = (c & 8) | ((c ^ r) & 7);                                    \
            cp16(Bs + (stage) * 8192 + r * 128 + (sw << 3),                      \
                 W + (size_t)((kc) + r) * ldw + n0 + c * 8);                     \
        }                                                                        \
    }

    LOAD_A(0, 0); LOAD_B(0, 0); cp_commit();
    if (nk > 1) { LOAD_A(1, 64); LOAD_B(1, 64); cp_commit(); }

    for (int k = 0; k < nk; k++) {
        int cur = k % 3;
        if (k + 2 < nk) {
            int nxt = (k + 2) % 3;
            LOAD_A(nxt, (k + 2) * 64);
            LOAD_B(nxt, (k + 2) * 64);
            cp_commit();
            cp_wait<2>();
        } else if (k + 1 < nk) {
            cp_wait<1>();
        } else {
            cp_wait<0>();
        }
        __syncthreads();
        const __half* Ab = As + cur * 8192;
        const __half* Bb = Bs + cur * 8192;
#pragma unroll
        for (int ks = 0; ks < 4; ks++) {
            uint32_t a[4][4], b[2][4];
#pragma unroll
            for (int mi = 0; mi < 4; mi++) {
                int m = wm + mi * 16 + (lane & 15);
                int kch = ks * 2 + (lane >> 4);
                ldm_x4(a[mi], smem_u32(Ab + m * 64 + (((kch ^ m) & 7) << 3)));
            }
#pragma unroll
            for (int ni = 0; ni < 2; ni++) {
                int kk = ks * 16 + (lane & 15);
                int nch = (wn >> 3) + ni * 2 + (lane >> 4);
                int sw = (nch & 8) | ((nch ^ kk) & 7);
                ldm_x4_t(b[ni], smem_u32(Bb + kk * 128 + (sw << 3)));
            }
#pragma unroll
            for (int mi = 0; mi < 4; mi++)
#pragma unroll
                for (int ni = 0; ni < 4; ni++)
                    mma16816(acc[mi][ni], a[mi], &b[ni >> 1][(ni & 1) * 2]);
        }
        __syncthreads();
    }
#undef LOAD_A
#undef LOAD_B

#pragma unroll
    for (int mi = 0; mi < 4; mi++) {
#pragma unroll
        for (int hh = 0; hh < 2; hh++) {
            int m = m0 + wm + mi * 16 + (lane >> 2) + hh * 8;
            if (m >= M) continue;
            int active = 1, bo = 0, to = 0;
            if (MODE == 3) {
                to = m >> 8; bo = m & 255;
                active = (lens[bo] > to);
            }
#pragma unroll
            for (int ni = 0; ni < 4; ni++) {
                int col = n0 + wn + ni * 8 + (lane & 3) * 2;
#pragma unroll
                for (int j = 0; j < 2; j++) {
                    int n = col + j;
                    float v = acc[mi][ni][hh * 2 + j];
                    if (bias) v += bias[n];
                    if (MODE == 0) {
                        Cf[(size_t)m * ldc + n] = v;
                    } else if (MODE == 3) {
                        if (active && n < N)
                            Cf[((size_t)bo * TT + to) * ldc + n] = v;
                    } else {
                        Ch[(size_t)m * ldc + n] = __float2half(v);
                    }
                }
            }
        }
    }
}

// ================= MF=2 combined pre-attention kernel =================
// Grid (22, 4), m0 = by*64. All blocks share the SAME A (h = g_xh cols 256..767, K=512).
//   bx < 6 : AG   — B = g_wag cols bx*128..,    epilogue: +bag, sigmoid(n>=512) -> g_ag
//   bx >= 6: GH   — B = g_wg rows 256.. (whh) at gate-strip cols of s0=bx-6,
//                   epilogue: raw partial -> g_gates (gate-strip layout)
__global__ __launch_bounds__(256)
void ag2_k()
{
    extern __shared__ __half sm[];
    __half* As = sm;             // 3 stages * 4096 halves
    __half* Bs = sm + 12288;     // 3 stages * 8192 halves
    const int tid = threadIdx.x;
    const int warp = tid >> 5, lane = tid & 31;
    const int wm = (warp & 1) * 32, wn = (warp >> 1) * 32;
    const int m0 = blockIdx.y * 64;
    const int bx = blockIdx.x;
    const bool isAG = (bx < 6);
    const int n0 = isAG ? bx * 128 : 0;
    const int s0 = isAG ? 0 : (bx - 6) * 32;   // gate-strip d0 for GH blocks

    float acc[2][4][4];
#pragma unroll
    for (int i = 0; i < 2; i++)
#pragma unroll
        for (int j = 0; j < 4; j++)
#pragma unroll
            for (int k = 0; k < 4; k++) acc[i][j][k] = 0.f;

    const int nk = 8;   // K=512

#define A2LOAD_A(stage, kc)                                                      \
    {                                                                            \
        _Pragma("unroll")                                                        \
        for (int i = 0; i < 2; i++) {                                            \
            int idx = tid + i * 256;                                             \
            int r = idx >> 3, c = idx & 7;                                       \
            cp16(As + (stage) * 4096 + r * 64 + (((c ^ r) & 7) << 3),            \
                 g_xh + (size_t)(m0 + r) * 768 + 256 + (kc) + c * 8);            \
        }                                                                        \
    }
#define A2LOAD_B(stage, kc)                                                      \
    {                                                                            \
        _Pragma("unroll")                                                        \
        for (int i = 0; i < 4; i++) {                                            \
            int idx = tid + i * 256;                                             \
            int r = idx >> 4, c = idx & 15;                                      \
            int sw = (c & 8) | ((c ^ r) & 7);                                    \
            const __half* src;                                                   \
            if (isAG) src = g_wag + (size_t)((kc) + r) * 768 + n0 + c * 8;       \
            else {                                                               \
                int gcol = ((c >> 2) << 9) + s0 + ((c & 3) << 3);                \
                src = g_wg + (size_t)(256 + (kc) + r) * GG + gcol;               \
            }                                                                    \
            cp16(Bs + (stage) * 8192 + r * 128 + (sw << 3), src);                \
        }                                                                        \
    }

    A2LOAD_A(0, 0); A2LOAD_B(0, 0); cp_commit();
    A2LOAD_A(1, 64); A2LOAD_B(1, 64); cp_commit();

    for (int k = 0; k < nk; k++) {
        int cur = k % 3;
        if (k + 2 < nk) {
            int nxt = (k + 2) % 3;
            A2LOAD_A(nxt, (k + 2) * 64);
            A2LOAD_B(nxt, (k + 2) * 64);
            cp_commit();
            cp_wait<2>();
        } else if (k + 1 < nk) {
            cp_wait<1>();
        } else {
            cp_wait<0>();
        }
        __syncthreads();
        const __half* Ab = As + cur * 4096;
        const __half* Bb = Bs + cur * 8192;
#pragma unroll
        for (int ks = 0; ks < 4; ks++) {
            uint32_t a[2][4], b[2][4];
#pragma unroll
            for (int mi = 0; mi < 2; mi++) {
                int m = wm + mi * 16 + (lane & 15);
                int kch = ks * 2 + (lane >> 4);
                ldm_x4(a[mi], smem_u32(Ab + m * 64 + (((kch ^ m) & 7) << 3)));
            }
#pragma unroll
            for (int ni = 0; ni < 2; ni++) {
                int kk = ks * 16 + (lane & 15);
                int nch = (wn >> 3) + ni * 2 + (lane >> 4);
                int sw = (nch & 8) | ((nch ^ kk) & 7);
                ldm_x4_t(b[ni], smem_u32(Bb + kk * 128 + (sw << 3)));
            }
#pragma unroll
            for (int mi = 0; mi < 2; mi++)
#pragma unroll
                for (int ni = 0; ni < 4; ni++)
                    mma16816(acc[mi][ni], a[mi], &b[ni >> 1][(ni & 1) * 2]);
        }
        __syncthreads();
    }
#undef A2LOAD_A
#undef A2LOAD_B

#pragma unroll
    for (int mi = 0; mi < 2; mi++) {
#pragma unroll
        for (int hh = 0; hh < 2; hh++) {
            int m = m0 + wm + mi * 16 + (lane >> 2) + hh * 8;
#pragma unroll
            for (int ni = 0; ni < 4; ni++) {
                int coll = wn + ni * 8 + (lane & 3) * 2;
#pragma unroll
                for (int j = 0; j < 2; j++) {
                    int nl = coll + j;
                    float v = acc[mi][ni][hh * 2 + j];
                    if (isAG) {
                        int n = n0 + nl;
                        v += g_bag[n];
                        if (n >= 512) v = sigmoidf(v);
                        g_ag[m * 768 + n] = v;
                    } else {
                        int gcol = ((nl >> 5) << 9) + s0 + (nl & 31);
                        g_gates[m * GG + gcol] = v;
                    }
                }
            }
        }
    }
}

// ================= MF=2 fused gates(xg part, K=256) + LSTM cell =================
// Grid (16, 4): m0 = by*64, d0 = bx*32. Cols = 4 gate strips of 32.
// acc += g_gates partial (h@Whh, computed pre-attention) in epilogue.
__global__ __launch_bounds__(256)
void gates_cell_k(const float* __restrict__ bih, const float* __restrict__ bhh,
                  const int* __restrict__ caps,
                  const float* __restrict__ cold, float* __restrict__ cnew, int t)
{
    extern __shared__ __half sm[];
    __half* As = sm;
    __half* Bs = sm + 12288;
    const int tid = threadIdx.x;
    const int warp = tid >> 5, lane = tid & 31;
    const int wm = (warp & 1) * 32, wn = (warp >> 1) * 32;
    const int m0 = blockIdx.y * 64;
    const int d0 = blockIdx.x * 32;

    float acc[2][4][4];
#pragma unroll
    for (int i = 0; i < 2; i++)
#pragma unroll
        for (int j = 0; j < 4; j++)
#pragma unroll
            for (int k = 0; k < 4; k++) acc[i][j][k] = 0.f;

    const int nk = 4;   // K=256 (xg part only)

#define GLOAD_A(stage, kc)                                                       \
    {                                                                            \
        _Pragma("unroll")                                                        \
        for (int i = 0; i < 2; i++) {                                            \
            int idx = tid + i * 256;                                             \
            int r = idx >> 3, c = idx & 7;                                       \
            cp16(As + (stage) * 4096 + r * 64 + (((c ^ r) & 7) << 3),            \
                 g_xh + (size_t)(m0 + r) * 768 + (kc) + c * 8);                  \
        }                                                                        \
    }
#define GLOAD_B(stage, kc)                                                       \
    {                                                                            \
        _Pragma("unroll")                                                        \
        for (int i = 0; i < 4; i++) {                                            \
            int idx = tid + i * 256;                                             \
            int r = idx >> 4, c = idx & 15;                                      \
            int sw = (c & 8) | ((c ^ r) & 7);                                    \
            int gcol = ((c >> 2) << 9) + d0 + ((c & 3) << 3);                    \
            cp16(Bs + (stage) * 8192 + r * 128 + (sw << 3),                      \
                 g_wg + (size_t)((kc) + r) * GG + gcol);                         \
        }                                                                        \
    }

    GLOAD_A(0, 0); GLOAD_B(0, 0); cp_commit();
    GLOAD_A(1, 64); GLOAD_B(1, 64); cp_commit();

    for (int k = 0; k < nk; k++) {
        int cur = k % 3;
        if (k + 2 < nk) {
            int nxt = (k + 2) % 3;
            GLOAD_A(nxt, (k + 2) * 64);
            GLOAD_B(nxt, (k + 2) * 64);
            cp_commit();
            cp_wait<2>();
        } else if (k + 1 < nk) {
            cp_wait<1>();
        } else {
            cp_wait<0>();
        }
        __syncthreads();
        const __half* Ab = As + cur * 4096;
        const __half* Bb = Bs + cur * 8192;
#pragma unroll
        for (int ks = 0; ks < 4; ks++) {
            uint32_t a[2][4], b[2][4];
#pragma unroll
            for (int mi = 0; mi < 2; mi++) {
                int m = wm + mi * 16 + (lane & 15);
                int kch = ks * 2 + (lane >> 4);
                ldm_x4(a[mi], smem_u32(Ab + m * 64 + (((kch ^ m) & 7) << 3)));
            }
#pragma unroll
            for (int ni = 0; ni < 2; ni++) {
                int kk = ks * 16 + (lane & 15);
                int nch = (wn >> 3) + ni * 2 + (lane >> 4);
                int sw = (nch & 8) | ((nch ^ kk) & 7);
                ldm_x4_t(b[ni], smem_u32(Bb + kk * 128 + (sw << 3)));
            }
#pragma unroll
            for (int mi = 0; mi < 2; mi++)
#pragma unroll
                for (int ni = 0; ni < 4; ni++)
                    mma16816(acc[mi][ni], a[mi], &b[ni >> 1][(ni & 1) * 2]);
        }
        __syncthreads();
    }
#undef GLOAD_A
#undef GLOAD_B

    // stage pre-activations (+partial+biases+embW) to smem, then cell
    float* smf = reinterpret_cast<float*>(sm);   // 64 x 132 floats = 33.8 KB
#pragma unroll
    for (int mi = 0; mi < 2; mi++) {
#pragma unroll
        for (int hh = 0; hh < 2; hh++) {
            int ml = wm + mi * 16 + (lane >> 2) + hh * 8;
            int eidx = caps[(m0 + ml) * TT + t];
#pragma unroll
            for (int ni = 0; ni < 4; ni++) {
#pragma unroll
                for (int j = 0; j < 2; j++) {
                    int nl = wn + ni * 8 + (lane & 3) * 2 + j;
                    int gcol = ((nl >> 5) << 9) + d0 + (nl & 31);
                    smf[ml * 132 + nl] = acc[mi][ni][hh * 2 + j]
                        + g_gates[(m0 + ml) * GG + gcol]
                        + bih[gcol] + bhh[gcol] + g_embW[(size_t)eidx * GG + gcol];
                }
            }
        }
    }
    __syncthreads();

    for (int e = tid; e < 64 * 32; e += 256) {
        int ml = e >> 5, dl = e & 31;
        float iv = smf[ml * 132 + dl];
        float fv = smf[ml * 132 + 32 + dl];
        float gv = smf[ml * 132 + 64 + dl];
        float ov = smf[ml * 132 + 96 + dl];
        int b = m0 + ml, d = d0 + dl;
        float c = sigmoidf(fv) * cold[b * DECD + d] + sigmoidf(iv) * tanhf(gv);
        cnew[b * DECD + d] = c;
        __half hh = __float2half(sigmoidf(ov) * tanhf(c));
        g_xh[b * 768 + 256 + d] = hh;
        g_hall[((size_t)t * BB + b) * DECD + d] = hh;
    }
}

// ================= small kernels =================
__global__ void cvt_k(const float* __restrict__ src, __half* __restrict__ dst,
                      int rows, int cols, int sld, int dld, int valid)
{
    int n = rows * cols;
    for (int i = blockIdx.x * blockDim.x + threadIdx.x; i < n; i += gridDim.x * blockDim.x) {
        int r = i / cols, c = i - r * cols;
        float v = (c < valid) ? src[(size_t)r * sld + c] : 0.f;
        dst[(size_t)r * dld + c] = __float2half(v);
    }
}

__global__ void mean_k(const float* __restrict__ enc)
{
    int b = blockIdx.x, e = threadIdx.x;
    const float* p = enc + (size_t)b * PP * ENCD + e;
    float s = 0.f;
#pragma unroll 8
    for (int pp = 0; pp < PP; pp++) s += p[(size_t)pp * ENCD];
    g_mean16[b * ENCD + e] = __float2half(s * (1.f / PP));
}

__global__ void bag_k(const float* __restrict__ b1, const float* __restrict__ b2)
{
    int i = threadIdx.x + blockIdx.x * blockDim.x;
    if (i < 512) g_bag[i] = b1[i];
    else if (i < 768) g_bag[i] = b2[i - 512];
}

__global__ void h0c_k()
{
    int b = blockIdx.x, d = threadIdx.x;
    g_xh[b * 768 + 256 + d] = __float2half(g_h[b * DECD + d]);
}

__global__ void lens_k(const int* __restrict__ lens, float* __restrict__ o)
{
    o[threadIdx.x] = (float)lens[threadIdx.x];
}

// fused attention: e -> softmax -> awe -> xg(fp16)
__global__ __launch_bounds__(256)
void attention_k(const float* __restrict__ wfull, const int* __restrict__ lens,
                 int t, float* __restrict__ alphas_out)
{
    __shared__ float att2s[DECD];
    __shared__ float wf[DECD];
    __shared__ float es[PP];
    __shared__ float red[32];
    int b = blockIdx.x, tid = threadIdx.x;
    att2s[tid]       = g_ag[b * 768 + tid];
    att2s[tid + 256] = g_ag[b * 768 + 256 + tid];
    wf[tid]       = wfull[tid];
    wf[tid + 256] = wfull[tid + 256];
    __syncthreads();

    int warp = tid >> 5, lane = tid & 31;
    const __half2* a1 = reinterpret_cast<const __half2*>(g_att1 + (size_t)b * PP * DECD);
    for (int p = warp; p < PP; p += 8) {
        const __half2* row = a1 + (size_t)p * (DECD / 2);
        float acc = 0.f;
#pragma unroll
        for (int i = 0; i < DECD / 64; i++) {
            int d2 = lane + 32 * i;
            float2 v = __half22float2(row[d2]);
            float x0 = v.x + att2s[2 * d2];
            float x1 = v.y + att2s[2 * d2 + 1];
            acc += fmaxf(x0, 0.f) * wf[2 * d2] + fmaxf(x1, 0.f) * wf[2 * d2 + 1];
        }
#pragma unroll
        for (int o = 16; o > 0; o >>= 1) acc += __shfl_xor_sync(0xffffffffu, acc, o);
        if (lane == 0) es[p] = acc;
    }
    __syncthreads();

    float e = es[tid];
    float m = e;
#pragma unroll
    for (int o = 16; o > 0; o >>= 1) m = fmaxf(m, __shfl_xor_sync(0xffffffffu, m, o));
    if (lane == 0) red[warp] = m;
    __syncthreads();
    if (tid == 0) {
        float mm = red[0];
        for (int w = 1; w < 8; w++) mm = fmaxf(mm, red[w]);
        red[16] = mm;
    }
    __syncthreads();
    float ex = expf(e - red[16]);
    float s = ex;
#pragma unroll
    for (int o = 16; o > 0; o >>= 1) s += __shfl_xor_sync(0xffffffffu, s, o);
    if (lane == 0) red[warp] = s;
    __syncthreads();
    if (tid == 0) {
        float ss = 0.f;
        for (int w = 0; w < 8; w++) ss += red[w];
        red[17] = ss;
    }
    __syncthreads();
    float alpha = ex / red[17];
    es[tid] = alpha;
    int active = lens[b] > t;
    alphas_out[((size_t)b * TT + t) * PP + tid] = active ? alpha : 0.f;
    __syncthreads();

    const __half* eb = g_encb + (size_t)b * PP * ENCD;
    float acc = 0.f;
#pragma unroll 8
    for (int p = 0; p < PP; p++) acc += es[p] * __half2float(eb[(size_t)p * ENCD + tid]);
    float gate = g_ag[b * 768 + 512 + tid];
    g_xh[b * 768 + tid] = __float2half(gate * acc);
}

// ================= host orchestration =================
static inline int cgrid(int n) { int g = (n + 255) / 256; return g > 4096 ? 4096 : g; }

extern "C" void kernel_launch(void* const* d_in, const int* in_sizes, int n_in,
                              void* d_out, int out_size)
{
    const float* enc        = (const float*)d_in[0];
    const int*   caps       = (const int*)d_in[1];
    const int*   lens       = (const int*)d_in[2];
    const float* embedding  = (const float*)d_in[3];
    const float* enc_att_w  = (const float*)d_in[4];
    const float* enc_att_b  = (const float*)d_in[5];
    const float* dec_att_w  = (const float*)d_in[6];
    const float* dec_att_b  = (const float*)d_in[7];
    const float* full_att_w = (const float*)d_in[8];
    const float* lstm_wih   = (const float*)d_in[10];
    const float* lstm_whh   = (const float*)d_in[11];
    const float* lstm_bih   = (const float*)d_in[12];
    const float* lstm_bhh   = (const float*)d_in[13];
    const float* init_h_w   = (const float*)d_in[14];
    const float* init_h_b   = (const float*)d_in[15];
    const float* init_c_w   = (const float*)d_in[16];
    const float* init_c_b   = (const float*)d_in[17];
    const float* f_beta_w   = (const float*)d_in[18];
    const float* f_beta_b   = (const float*)d_in[19];
    const float* fc_w       = (const float*)d_in[20];
    const float* fc_b       = (const float*)d_in[21];

    float* out      = (float*)d_out;
    float* out_pred = out;
    float* out_lens = out + (size_t)BB * TT * VV;
    float* out_alph = out_lens + BB;

    cudaFuncSetAttribute(hgemm_k<0>, cudaFuncAttributeMaxDynamicSharedMemorySize, SMEMSZ);
    cudaFuncSetAttribute(hgemm_k<3>, cudaFuncAttributeMaxDynamicSharedMemorySize, SMEMSZ);
    cudaFuncSetAttribute(hgemm_k<4>, cudaFuncAttributeMaxDynamicSharedMemorySize, SMEMSZ);
    cudaFuncSetAttribute(ag2_k, cudaFuncAttributeMaxDynamicSharedMemorySize, SMEMSZ2);
    cudaFuncSetAttribute(gates_cell_k, cudaFuncAttributeMaxDynamicSharedMemorySize, SMEMSZ2);

    cudaStream_t s2;
    cudaStreamCreateWithFlags(&s2, cudaStreamNonBlocking);
    cudaEvent_t evA[TT / 8], evB[TT / 8], evP, evF;
    for (int i = 0; i < TT / 8; i++) {
        cudaEventCreateWithFlags(&evA[i], cudaEventDisableTiming);
        cudaEventCreateWithFlags(&evB[i], cudaEventDisableTiming);
    }
    cudaEventCreateWithFlags(&evP, cudaEventDisableTiming);
    cudaEventCreateWithFlags(&evF, cudaEventDisableTiming);

    __half *p_encb, *p_emb16, *p_xh, *p_hall, *p_mean16, *p_att1;
    __half *p_wag, *p_wg, *p_wtop, *p_wfc, *p_wenc, *p_wih0, *p_wic0;
    float *p_h, *p_c, *p_ag, *p_embW, *p_bag;
    cudaGetSymbolAddress((void**)&p_encb, g_encb);
    cudaGetSymbolAddress((void**)&p_emb16, g_emb16);
    cudaGetSymbolAddress((void**)&p_xh, g_xh);
    cudaGetSymbolAddress((void**)&p_hall, g_hall);
    cudaGetSymbolAddress((void**)&p_mean16, g_mean16);
    cudaGetSymbolAddress((void**)&p_att1, g_att1);
    cudaGetSymbolAddress((void**)&p_wag, g_wag);
    cudaGetSymbolAddress((void**)&p_wg, g_wg);
    cudaGetSymbolAddress((void**)&p_wtop, g_wtop);
    cudaGetSymbolAddress((void**)&p_wfc, g_wfc);
    cudaGetSymbolAddress((void**)&p_wenc, g_wenc);
    cudaGetSymbolAddress((void**)&p_wih0, g_wih0);
    cudaGetSymbolAddress((void**)&p_wic0, g_wic0);
    cudaGetSymbolAddress((void**)&p_h, g_h);
    cudaGetSymbolAddress((void**)&p_c, g_c);
    cudaGetSymbolAddress((void**)&p_ag, g_ag);
    cudaGetSymbolAddress((void**)&p_embW, g_embW);
    cudaGetSymbolAddress((void**)&p_bag, g_bag);

    // capture-legal fork of s2
    cudaEventRecord(evF, 0);
    cudaStreamWaitEvent(s2, evF, 0);

    // s2: embW precompute chain, then prediction-region memset
    cvt_k<<<cgrid(VV * EE), 256, 0, s2>>>(embedding, p_emb16, VV, EE, EE, EE, EE);
    cvt_k<<<cgrid(256 * GG), 256, 0, s2>>>(lstm_wih, p_wtop, 256, GG, GG, GG, GG);
    hgemm_k<0><<<dim3(GG / 128, (VV + 127) / 128), 256, SMEMSZ, s2>>>(p_emb16, EE, p_wtop, GG,
        nullptr, p_embW, nullptr, GG, VV, GG, EE, nullptr, 0);
    cudaEventRecord(evP, s2);
    cudaMemsetAsync(out_pred, 0, (size_t)BB * TT * VV * sizeof(float), s2);

    // stream 0: remaining conversions
    cvt_k<<<cgrid(BB * PP * ENCD), 256>>>(enc, p_encb, BB * PP, ENCD, ENCD, ENCD, ENCD);
    cvt_k<<<cgrid(512 * 512), 256>>>(dec_att_w, p_wag, 512, 512, 512, 768, 512);
    cvt_k<<<cgrid(512 * 256), 256>>>(f_beta_w, p_wag + 512, 512, 256, 256, 768, 256);
    cvt_k<<<cgrid(256 * GG), 256>>>(lstm_wih + (size_t)EE * GG, p_wg, 256, GG, GG, GG, GG);
    cvt_k<<<cgrid(512 * GG), 256>>>(lstm_whh, p_wg + (size_t)256 * GG, 512, GG, GG, GG, GG);
    cvt_k<<<cgrid(512 * VPAD), 256>>>(fc_w, p_wfc, 512, VPAD, VV, VPAD, VV);
    cvt_k<<<cgrid(256 * 512), 256>>>(enc_att_w, p_wenc, 256, 512, 512, 512, 512);
    cvt_k<<<cgrid(256 * 512), 256>>>(init_h_w, p_wih0, 256, 512, 512, 512, 512);
    cvt_k<<<cgrid(256 * 512), 256>>>(init_c_w, p_wic0, 256, 512, 512, 512, 512);
    bag_k<<<3, 256>>>(dec_att_b, f_beta_b);
    mean_k<<<BB, 256>>>(enc);

    // one-time TC GEMMs
    hgemm_k<0><<<dim3(DECD / 128, BB / 128), 256, SMEMSZ>>>(p_mean16, ENCD, p_wih0, DECD,
        init_h_b, p_h, nullptr, DECD, BB, DECD, ENCD, nullptr, 0);
    hgemm_k<0><<<dim3(DECD / 128, BB / 128), 256, SMEMSZ>>>(p_mean16, ENCD, p_wic0, DECD,
        init_c_b, p_c, nullptr, DECD, BB, DECD, ENCD, nullptr, 0);
    h0c_k<<<BB, DECD>>>();
    hgemm_k<4><<<dim3(DECD / 128, (BB * PP) / 128), 256, SMEMSZ>>>(p_encb, ENCD, p_wenc, DECD,
        enc_att_b, nullptr, p_att1, DECD, BB * PP, DECD, ENCD, nullptr, 0);
    lens_k<<<1, BB>>>(lens, out_lens);

    // join s2 precompute (embW needed by gates_cell at t=0)
    cudaStreamWaitEvent(0, evP, 0);

    // timestep loop: 3 launches/step; gates K-split across the attention boundary
    for (int t = 0; t < TT; t++) {
        const float* ccur = p_c + (t & 1) * (BB * DECD);
        float*       cnext = p_c + ((t + 1) & 1) * (BB * DECD);

        ag2_k<<<dim3(22, 4), 256, SMEMSZ2>>>();
        attention_k<<<BB, 256>>>(full_att_w, lens, t, out_alph);
        gates_cell_k<<<dim3(16, 4), 256, SMEMSZ2>>>(lstm_bih, lstm_bhh, caps, ccur, cnext, t);

        if ((t & 7) == 7) {
            int c = t >> 3;
            cudaEventRecord(evA[c], 0);
            cudaStreamWaitEvent(s2, evA[c], 0);
            hgemm_k<3><<<dim3(VPAD / 128, 16), 256, SMEMSZ, s2>>>(p_hall, DECD, p_wfc, VPAD,
                fc_b, out_pred, nullptr, VV, BB * TT, VV, DECD, lens, c * 8 * BB);
            cudaEventRecord(evB[c], s2);
        }
    }

    for (int c = 0; c < TT / 8; c++) cudaStreamWaitEvent(0, evB[c], 0);
}

// round 17
// speedup vs baseline: 1.7804x; 1.0841x over previous
#include <cuda_runtime.h>
#include <cuda_fp16.h>
#include <cstddef>
#include <cstdint>

#define BB   256
#define PP   256
#define ENCD 256
#define DECD 512
#define EE   256
#define VV   5000
#define TT   96
#define GG   2048
#define VPAD 5120

#define SMEMSZ 98304    // MF=4: 3*(128*64 + 64*128) halves = 96 KB
#define SMEMSZ2 73728   // MF=2: 3*(64*64 + 64*128) halves = 72 KB

// ---------------- device scratch ----------------
__device__ __half g_att1[(size_t)BB * PP * DECD];
__device__ __half g_encb[(size_t)BB * PP * ENCD];   // row-major fp16 enc (att1 GEMM A)
__device__ __half g_encbT[(size_t)BB * ENCD * PP];  // transposed [b][e][p] (awe pass)
__device__ float  g_embW[(size_t)VV * GG];
__device__ __half g_emb16[(size_t)VV * EE];
__device__ __half g_hall[(size_t)BB * TT * DECD];   // t-major
__device__ __half g_xh[BB * (ENCD + DECD)];         // [xg | h], ld=768
__device__ float  g_h[BB * DECD];
__device__ float  g_c[2 * BB * DECD];
__device__ float  g_ag[BB * 768];
__device__ float  g_gates[BB * GG];                 // h@Whh partial (gate-strip cols)
__device__ __half g_mean16[BB * ENCD];
__device__ float  g_bag[768];
__device__ __half g_wag[512 * 768];
__device__ __half g_wg[768 * GG];                   // rows 0..255: wih_bot; 256..767: whh
__device__ __half g_wtop[256 * GG];
__device__ __half g_wfc[512 * VPAD];
__device__ __half g_wenc[256 * 512];
__device__ __half g_wih0[256 * 512];
__device__ __half g_wic0[256 * 512];

__device__ __forceinline__ float sigmoidf(float x) { return 1.f / (1.f + expf(-x)); }

__device__ __forceinline__ uint32_t smem_u32(const void* p) {
    return (uint32_t)__cvta_generic_to_shared(p);
}
__device__ __forceinline__ void cp16(void* dst, const void* src) {
    asm volatile("cp.async.cg.shared.global [%0], [%1], 16;"
                 :: "r"(smem_u32(dst)), "l"(src));
}
__device__ __forceinline__ void cp_commit() { asm volatile("cp.async.commit_group;"); }
template<int N>
__device__ __forceinline__ void cp_wait() { asm volatile("cp.async.wait_group %0;" :: "n"(N)); }

__device__ __forceinline__ void ldm_x4(uint32_t* r, uint32_t addr) {
    asm volatile("ldmatrix.sync.aligned.m8n8.x4.shared.b16 {%0,%1,%2,%3}, [%4];"
                 : "=r"(r[0]), "=r"(r[1]), "=r"(r[2]), "=r"(r[3]) : "r"(addr));
}
__device__ __forceinline__ void ldm_x4_t(uint32_t* r, uint32_t addr) {
    asm volatile("ldmatrix.sync.aligned.m8n8.x4.trans.shared.b16 {%0,%1,%2,%3}, [%4];"
                 : "=r"(r[0]), "=r"(r[1]), "=r"(r[2]), "=r"(r[3]) : "r"(addr));
}
__device__ __forceinline__ void mma16816(float* c, const uint32_t* a, const uint32_t* b) {
    asm volatile("mma.sync.aligned.m16n8k16.row.col.f32.f16.f16.f32 "
                 "{%0,%1,%2,%3},{%4,%5,%6,%7},{%8,%9},{%0,%1,%2,%3};"
                 : "+f"(c[0]), "+f"(c[1]), "+f"(c[2]), "+f"(c[3])
                 : "r"(a[0]), "r"(a[1]), "r"(a[2]), "r"(a[3]), "r"(b[0]), "r"(b[1]));
}

// ================= MF=4 (128-row) GEMM: precompute + fc =================
// MODE: 0 fp32(+bias) | 3 fc t-major (tile skip, masked) | 4 fp16 out (+bias)
template<int MODE>
__global__ __launch_bounds__(256)
void hgemm_k(const __half* __restrict__ A, int lda,
             const __half* __restrict__ W, int ldw,
             const float* __restrict__ bias,
             float* __restrict__ Cf, __half* __restrict__ Ch, int ldc,
             int M, int N, int K,
             const int* __restrict__ lens, int t)
{
    extern __shared__ __half sm[];
    __half* As = sm;
    __half* Bs = sm + 24576;
    const int tid = threadIdx.x;
    const int warp = tid >> 5, lane = tid & 31;
    const int wm = (warp & 1) * 64, wn = (warp >> 1) * 32;
    const int m0 = blockIdx.y * 128 + (MODE == 3 ? t : 0);
    const int n0 = blockIdx.x * 128;

    if (MODE == 3) {
        int tt = m0 >> 8, bmin = m0 & 255;
        if (lens[bmin] <= tt) return;
    }

    float acc[4][4][4];
#pragma unroll
    for (int i = 0; i < 4; i++)
#pragma unroll
        for (int j = 0; j < 4; j++)
#pragma unroll
            for (int k = 0; k < 4; k++) acc[i][j][k] = 0.f;

    const int nk = K >> 6;

#define LOAD_A(stage, kc)                                                        \
    {                                                                            \
        _Pragma("unroll")                                                        \
        for (int i = 0; i < 4; i++) {                                            \
            int idx = tid + i * 256;                                             \
            int r = idx >> 3, c = idx & 7;                                       \
            int gm = m0 + r; if (gm >= M) gm = M - 1;                            \
            cp16(As + (stage) * 8192 + r * 64 + (((c ^ r) & 7) << 3),            \
                 A + (size_t)gm * lda + (kc) + c * 8);                           \
        }                                                                        \
    }
#define LOAD_B(stage, kc)                                                        \
    {                                                                            \
        _Pragma("unroll")                                                        \
        for (int i = 0; i < 4; i++) {                                            \
            int idx = tid + i * 256;                                             \
            int r = idx >> 4, c = idx & 15;                                      \
            int sw = (c & 8) | ((c ^ r) & 7);                                    \
            cp16(Bs + (stage) * 8192 + r * 128 + (sw << 3),                      \
                 W + (size_t)((kc) + r) * ldw + n0 + c * 8);                     \
        }                                                                        \
    }

    LOAD_A(0, 0); LOAD_B(0, 0); cp_commit();
    if (nk > 1) { LOAD_A(1, 64); LOAD_B(1, 64); cp_commit(); }

    for (int k = 0; k < nk; k++) {
        int cur = k % 3;
        if (k + 2 < nk) {
            int nxt = (k + 2) % 3;
            LOAD_A(nxt, (k + 2) * 64);
            LOAD_B(nxt, (k + 2) * 64);
            cp_commit();
            cp_wait<2>();
        } else if (k + 1 < nk) {
            cp_wait<1>();
        } else {
            cp_wait<0>();
        }
        __syncthreads();
        const __half* Ab = As + cur * 8192;
        const __half* Bb = Bs + cur * 8192;
#pragma unroll
        for (int ks = 0; ks < 4; ks++) {
            uint32_t a[4][4], b[2][4];
#pragma unroll
            for (int mi = 0; mi < 4; mi++) {
                int m = wm + mi * 16 + (lane & 15);
                int kch = ks * 2 + (lane >> 4);
                ldm_x4(a[mi], smem_u32(Ab + m * 64 + (((kch ^ m) & 7) << 3)));
            }
#pragma unroll
            for (int ni = 0; ni < 2; ni++) {
                int kk = ks * 16 + (lane & 15);
                int nch = (wn >> 3) + ni * 2 + (lane >> 4);
                int sw = (nch & 8) | ((nch ^ kk) & 7);
                ldm_x4_t(b[ni], smem_u32(Bb + kk * 128 + (sw << 3)));
            }
#pragma unroll
            for (int mi = 0; mi < 4; mi++)
#pragma unroll
                for (int ni = 0; ni < 4; ni++)
                    mma16816(acc[mi][ni], a[mi], &b[ni >> 1][(ni & 1) * 2]);
        }
        __syncthreads();
    }
#undef LOAD_A
#undef LOAD_B

#pragma unroll
    for (int mi = 0; mi < 4; mi++) {
#pragma unroll
        for (int hh = 0; hh < 2; hh++) {
            int m = m0 + wm + mi * 16 + (lane >> 2) + hh * 8;
            if (m >= M) continue;
            int active = 1, bo = 0, to = 0;
            if (MODE == 3) {
                to = m >> 8; bo = m & 255;
                active = (lens[bo] > to);
            }
#pragma unroll
            for (int ni = 0; ni < 4; ni++) {
                int col = n0 + wn + ni * 8 + (lane & 3) * 2;
#pragma unroll
                for (int j = 0; j < 2; j++) {
                    int n = col + j;
                    float v = acc[mi][ni][hh * 2 + j];
                    if (bias) v += bias[n];
                    if (MODE == 0) {
                        Cf[(size_t)m * ldc + n] = v;
                    } else if (MODE == 3) {
                        if (active && n < N)
                            Cf[((size_t)bo * TT + to) * ldc + n] = v;
                    } else {
                        Ch[(size_t)m * ldc + n] = __float2half(v);
                    }
                }
            }
        }
    }
}

// ================= MF=2 combined pre-attention kernel =================
// Grid (22, 4), m0 = by*64. All blocks share the SAME A (h = g_xh cols 256..767, K=512).
//   bx < 6 : AG — B = g_wag cols bx*128.., epilogue: +bag, sigmoid(n>=512) -> g_ag
//   bx >= 6: GH — B = whh at gate-strip cols of s0=bx-6, epilogue: partial -> g_gates
__global__ __launch_bounds__(256)
void ag2_k()
{
    extern __shared__ __half sm[];
    __half* As = sm;             // 3 stages * 4096 halves
    __half* Bs = sm + 12288;     // 3 stages * 8192 halves
    const int tid = threadIdx.x;
    const int warp = tid >> 5, lane = tid & 31;
    const int wm = (warp & 1) * 32, wn = (warp >> 1) * 32;
    const int m0 = blockIdx.y * 64;
    const int bx = blockIdx.x;
    const bool isAG = (bx < 6);
    const int n0 = isAG ? bx * 128 : 0;
    const int s0 = isAG ? 0 : (bx - 6) * 32;

    float acc[2][4][4];
#pragma unroll
    for (int i = 0; i < 2; i++)
#pragma unroll
        for (int j = 0; j < 4; j++)
#pragma unroll
            for (int k = 0; k < 4; k++) acc[i][j][k] = 0.f;

    const int nk = 8;   // K=512

#define A2LOAD_A(stage, kc)                                                      \
    {                                                                            \
        _Pragma("unroll")                                                        \
        for (int i = 0; i < 2; i++) {                                            \
            int idx = tid + i * 256;                                             \
            int r = idx >> 3, c = idx & 7;                                       \
            cp16(As + (stage) * 4096 + r * 64 + (((c ^ r) & 7) << 3),            \
                 g_xh + (size_t)(m0 + r) * 768 + 256 + (kc) + c * 8);            \
        }                                                                        \
    }
#define A2LOAD_B(stage, kc)                                                      \
    {                                                                            \
        _Pragma("unroll")                                                        \
        for (int i = 0; i < 4; i++) {                                            \
            int idx = tid + i * 256;                                             \
            int r = idx >> 4, c = idx & 15;                                      \
            int sw = (c & 8) | ((c ^ r) & 7);                                    \
            const __half* src;                                                   \
            if (isAG) src = g_wag + (size_t)((kc) + r) * 768 + n0 + c * 8;       \
            else {                                                               \
                int gcol = ((c >> 2) << 9) + s0 + ((c & 3) << 3);                \
                src = g_wg + (size_t)(256 + (kc) + r) * GG + gcol;               \
            }                                                                    \
            cp16(Bs + (stage) * 8192 + r * 128 + (sw << 3), src);                \
        }                                                                        \
    }

    A2LOAD_A(0, 0); A2LOAD_B(0, 0); cp_commit();
    A2LOAD_A(1, 64); A2LOAD_B(1, 64); cp_commit();

    for (int k = 0; k < nk; k++) {
        int cur = k % 3;
        if (k + 2 < nk) {
            int nxt = (k + 2) % 3;
            A2LOAD_A(nxt, (k + 2) * 64);
            A2LOAD_B(nxt, (k + 2) * 64);
            cp_commit();
            cp_wait<2>();
        } else if (k + 1 < nk) {
            cp_wait<1>();
        } else {
            cp_wait<0>();
        }
        __syncthreads();
        const __half* Ab = As + cur * 4096;
        const __half* Bb = Bs + cur * 8192;
#pragma unroll
        for (int ks = 0; ks < 4; ks++) {
            uint32_t a[2][4], b[2][4];
#pragma unroll
            for (int mi = 0; mi < 2; mi++) {
                int m = wm + mi * 16 + (lane & 15);
                int kch = ks * 2 + (lane >> 4);
                ldm_x4(a[mi], smem_u32(Ab + m * 64 + (((kch ^ m) & 7) << 3)));
            }
#pragma unroll
            for (int ni = 0; ni < 2; ni++) {
                int kk = ks * 16 + (lane & 15);
                int nch = (wn >> 3) + ni * 2 + (lane >> 4);
                int sw = (nch & 8) | ((nch ^ kk) & 7);
                ldm_x4_t(b[ni], smem_u32(Bb + kk * 128 + (sw << 3)));
            }
#pragma unroll
            for (int mi = 0; mi < 2; mi++)
#pragma unroll
                for (int ni = 0; ni < 4; ni++)
                    mma16816(acc[mi][ni], a[mi], &b[ni >> 1][(ni & 1) * 2]);
        }
        __syncthreads();
    }
#undef A2LOAD_A
#undef A2LOAD_B

#pragma unroll
    for (int mi = 0; mi < 2; mi++) {
#pragma unroll
        for (int hh = 0; hh < 2; hh++) {
            int m = m0 + wm + mi * 16 + (lane >> 2) + hh * 8;
#pragma unroll
            for (int ni = 0; ni < 4; ni++) {
                int coll = wn + ni * 8 + (lane & 3) * 2;
#pragma unroll
                for (int j = 0; j < 2; j++) {
                    int nl = coll + j;
                    float v = acc[mi][ni][hh * 2 + j];
                    if (isAG) {
                        int n = n0 + nl;
                        v += g_bag[n];
                        if (n >= 512) v = sigmoidf(v);
                        g_ag[m * 768 + n] = v;
                    } else {
                        int gcol = ((nl >> 5) << 9) + s0 + (nl & 31);
                        g_gates[m * GG + gcol] = v;
                    }
                }
            }
        }
    }
}

// ================= MF=2 fused gates(xg part, K=256) + LSTM cell =================
__global__ __launch_bounds__(256)
void gates_cell_k(const float* __restrict__ bih, const float* __restrict__ bhh,
                  const int* __restrict__ caps,
                  const float* __restrict__ cold, float* __restrict__ cnew, int t)
{
    extern __shared__ __half sm[];
    __half* As = sm;
    __half* Bs = sm + 12288;
    const int tid = threadIdx.x;
    const int warp = tid >> 5, lane = tid & 31;
    const int wm = (warp & 1) * 32, wn = (warp >> 1) * 32;
    const int m0 = blockIdx.y * 64;
    const int d0 = blockIdx.x * 32;

    float acc[2][4][4];
#pragma unroll
    for (int i = 0; i < 2; i++)
#pragma unroll
        for (int j = 0; j < 4; j++)
#pragma unroll
            for (int k = 0; k < 4; k++) acc[i][j][k] = 0.f;

    const int nk = 4;   // K=256 (xg part only)

#define GLOAD_A(stage, kc)                                                       \
    {                                                                            \
        _Pragma("unroll")                                                        \
        for (int i = 0; i < 2; i++) {                                            \
            int idx = tid + i * 256;                                             \
            int r = idx >> 3, c = idx & 7;                                       \
            cp16(As + (stage) * 4096 + r * 64 + (((c ^ r) & 7) << 3),            \
                 g_xh + (size_t)(m0 + r) * 768 + (kc) + c * 8);                  \
        }                                                                        \
    }
#define GLOAD_B(stage, kc)                                                       \
    {                                                                            \
        _Pragma("unroll")                                                        \
        for (int i = 0; i < 4; i++) {                                            \
            int idx = tid + i * 256;                                             \
            int r = idx >> 4, c = idx & 15;                                      \
            int sw = (c & 8) | ((c ^ r) & 7);                                    \
            int gcol = ((c >> 2) << 9) + d0 + ((c & 3) << 3);                    \
            cp16(Bs + (stage) * 8192 + r * 128 + (sw << 3),                      \
                 g_wg + (size_t)((kc) + r) * GG + gcol);                         \
        }                                                                        \
    }

    GLOAD_A(0, 0); GLOAD_B(0, 0); cp_commit();
    GLOAD_A(1, 64); GLOAD_B(1, 64); cp_commit();

    for (int k = 0; k < nk; k++) {
        int cur = k % 3;
        if (k + 2 < nk) {
            int nxt = (k + 2) % 3;
            GLOAD_A(nxt, (k + 2) * 64);
            GLOAD_B(nxt, (k + 2) * 64);
            cp_commit();
            cp_wait<2>();
        } else if (k + 1 < nk) {
            cp_wait<1>();
        } else {
            cp_wait<0>();
        }
        __syncthreads();
        const __half* Ab = As + cur * 4096;
        const __half* Bb = Bs + cur * 8192;
#pragma unroll
        for (int ks = 0; ks < 4; ks++) {
            uint32_t a[2][4], b[2][4];
#pragma unroll
            for (int mi = 0; mi < 2; mi++) {
                int m = wm + mi * 16 + (lane & 15);
                int kch = ks * 2 + (lane >> 4);
                ldm_x4(a[mi], smem_u32(Ab + m * 64 + (((kch ^ m) & 7) << 3)));
            }
#pragma unroll
            for (int ni = 0; ni < 2; ni++) {
                int kk = ks * 16 + (lane & 15);
                int nch = (wn >> 3) + ni * 2 + (lane >> 4);
                int sw = (nch & 8) | ((nch ^ kk) & 7);
                ldm_x4_t(b[ni], smem_u32(Bb + kk * 128 + (sw << 3)));
            }
#pragma unroll
            for (int mi = 0; mi < 2; mi++)
#pragma unroll
                for (int ni = 0; ni < 4; ni++)
                    mma16816(acc[mi][ni], a[mi], &b[ni >> 1][(ni & 1) * 2]);
        }
        __syncthreads();
    }
#undef GLOAD_A
#undef GLOAD_B

    float* smf = reinterpret_cast<float*>(sm);   // 64 x 132 floats
#pragma unroll
    for (int mi = 0; mi < 2; mi++) {
#pragma unroll
        for (int hh = 0; hh < 2; hh++) {
            int ml = wm + mi * 16 + (lane >> 2) + hh * 8;
            int eidx = caps[(m0 + ml) * TT + t];
#pragma unroll
            for (int ni = 0; ni < 4; ni++) {
#pragma unroll
                for (int j = 0; j < 2; j++) {
                    int nl = wn + ni * 8 + (lane & 3) * 2 + j;
                    int gcol = ((nl >> 5) << 9) + d0 + (nl & 31);
                    smf[ml * 132 + nl] = acc[mi][ni][hh * 2 + j]
                        + g_gates[(m0 + ml) * GG + gcol]
                        + bih[gcol] + bhh[gcol] + g_embW[(size_t)eidx * GG + gcol];
                }
            }
        }
    }
    __syncthreads();

    for (int e = tid; e < 64 * 32; e += 256) {
        int ml = e >> 5, dl = e & 31;
        float iv = smf[ml * 132 + dl];
        float fv = smf[ml * 132 + 32 + dl];
        float gv = smf[ml * 132 + 64 + dl];
        float ov = smf[ml * 132 + 96 + dl];
        int b = m0 + ml, d = d0 + dl;
        float c = sigmoidf(fv) * cold[b * DECD + d] + sigmoidf(iv) * tanhf(gv);
        cnew[b * DECD + d] = c;
        __half hh = __float2half(sigmoidf(ov) * tanhf(c));
        g_xh[b * 768 + 256 + d] = hh;
        g_hall[((size_t)t * BB + b) * DECD + d] = hh;
    }
}

// ================= small kernels =================
__global__ void cvt_k(const float* __restrict__ src, __half* __restrict__ dst,
                      int rows, int cols, int sld, int dld, int valid)
{
    int n = rows * cols;
    for (int i = blockIdx.x * blockDim.x + threadIdx.x; i < n; i += gridDim.x * blockDim.x) {
        int r = i / cols, c = i - r * cols;
        float v = (c < valid) ? src[(size_t)r * sld + c] : 0.f;
        dst[(size_t)r * dld + c] = __float2half(v);
    }
}

// transpose encoder: enc [b][p][e] fp32 -> g_encbT [b][e][p] fp16
__global__ __launch_bounds__(256)
void trE_k(const float* __restrict__ enc)
{
    __shared__ float ts[32][33];
    int b = blockIdx.z;
    int p0 = blockIdx.y * 32, e0 = blockIdx.x * 32;
    int x = threadIdx.x & 31, y0 = threadIdx.x >> 5;
    const float* src = enc + (size_t)b * PP * ENCD;
#pragma unroll
    for (int j = 0; j < 4; j++) {
        int y = y0 + j * 8;
        ts[y][x] = src[(size_t)(p0 + y) * ENCD + e0 + x];
    }
    __syncthreads();
    __half* dst = g_encbT + (size_t)b * ENCD * PP;
#pragma unroll
    for (int j = 0; j < 4; j++) {
        int y = y0 + j * 8;
        dst[(size_t)(e0 + y) * PP + p0 + x] = __float2half(ts[x][y]);
    }
}

__global__ void mean_k(const float* __restrict__ enc)
{
    int b = blockIdx.x, e = threadIdx.x;
    const float* p = enc + (size_t)b * PP * ENCD + e;
    float s = 0.f;
#pragma unroll 8
    for (int pp = 0; pp < PP; pp++) s += p[(size_t)pp * ENCD];
    g_mean16[b * ENCD + e] = __float2half(s * (1.f / PP));
}

__global__ void bag_k(const float* __restrict__ b1, const float* __restrict__ b2)
{
    int i = threadIdx.x + blockIdx.x * blockDim.x;
    if (i < 512) g_bag[i] = b1[i];
    else if (i < 768) g_bag[i] = b2[i - 512];
}

__global__ void h0c_k()
{
    int b = blockIdx.x, d = threadIdx.x;
    g_xh[b * 768 + 256 + d] = __float2half(g_h[b * DECD + d]);
}

__global__ void lens_k(const int* __restrict__ lens, float* __restrict__ o)
{
    o[threadIdx.x] = (float)lens[threadIdx.x];
}

// fused attention: e -> softmax -> awe -> xg(fp16), vectorized 16B loads
__global__ __launch_bounds__(256)
void attention_k(const float* __restrict__ wfull, const int* __restrict__ lens,
                 int t, float* __restrict__ alphas_out)
{
    __shared__ float att2s[DECD];
    __shared__ float wf[DECD];
    __shared__ float es[PP];
    __shared__ float red[32];
    int b = blockIdx.x, tid = threadIdx.x;
    att2s[tid]       = g_ag[b * 768 + tid];
    att2s[tid + 256] = g_ag[b * 768 + 256 + tid];
    wf[tid]       = wfull[tid];
    wf[tid + 256] = wfull[tid + 256];
    __syncthreads();

    int warp = tid >> 5, lane = tid & 31;
    // e-pass: float4 loads of att1 rows (8 halves per load, 2 loads per row per lane)
    const float4* a1 = reinterpret_cast<const float4*>(g_att1 + (size_t)b * PP * DECD);
    for (int p = warp; p < PP; p += 8) {
        const float4* row = a1 + (size_t)p * (DECD / 8);
        float acc = 0.f;
#pragma unroll
        for (int i = 0; i < 2; i++) {
            int ch = lane + 32 * i;
            float4 v4 = row[ch];
            const __half2* hx = reinterpret_cast<const __half2*>(&v4);
            int base = ch * 8;
#pragma unroll
            for (int q = 0; q < 4; q++) {
                float2 v = __half22float2(hx[q]);
                acc += fmaxf(v.x + att2s[base + 2 * q], 0.f) * wf[base + 2 * q]
                     + fmaxf(v.y + att2s[base + 2 * q + 1], 0.f) * wf[base + 2 * q + 1];
            }
        }
#pragma unroll
        for (int o = 16; o > 0; o >>= 1) acc += __shfl_xor_sync(0xffffffffu, acc, o);
        if (lane == 0) es[p] = acc;
    }
    __syncthreads();

    float e = es[tid];
    float m = e;
#pragma unroll
    for (int o = 16; o > 0; o >>= 1) m = fmaxf(m, __shfl_xor_sync(0xffffffffu, m, o));
    if (lane == 0) red[warp] = m;
    __syncthreads();
    if (tid == 0) {
        float mm = red[0];
        for (int w = 1; w < 8; w++) mm = fmaxf(mm, red[w]);
        red[16] = mm;
    }
    __syncthreads();
    float ex = expf(e - red[16]);
    float s = ex;
#pragma unroll
    for (int o = 16; o > 0; o >>= 1) s += __shfl_xor_sync(0xffffffffu, s, o);
    if (lane == 0) red[warp] = s;
    __syncthreads();
    if (tid == 0) {
        float ss = 0.f;
        for (int w = 0; w < 8; w++) ss += red[w];
        red[17] = ss;
    }
    __syncthreads();
    float alpha = ex / red[17];
    es[tid] = alpha;
    int active = lens[b] > t;
    alphas_out[((size_t)b * TT + t) * PP + tid] = active ? alpha : 0.f;
    __syncthreads();

    // awe-pass: transposed encbT row per thread (e=tid), contiguous float4 loads
    const float4* ebT = reinterpret_cast<const float4*>(
        g_encbT + (size_t)b * ENCD * PP + (size_t)tid * PP);
    float acc = 0.f;
#pragma unroll 4
    for (int i = 0; i < PP / 8; i++) {
        float4 v4 = ebT[i];
        const __half2* hx = reinterpret_cast<const __half2*>(&v4);
        int base = i * 8;
#pragma unroll
        for (int q = 0; q < 4; q++) {
            float2 v = __half22float2(hx[q]);
            acc += es[base + 2 * q] * v.x + es[base + 2 * q + 1] * v.y;
        }
    }
    float gate = g_ag[b * 768 + 512 + tid];
    g_xh[b * 768 + tid] = __float2half(gate * acc);
}

// ================= host orchestration =================
static inline int cgrid(int n) { int g = (n + 255) / 256; return g > 4096 ? 4096 : g; }

extern "C" void kernel_launch(void* const* d_in, const int* in_sizes, int n_in,
                              void* d_out, int out_size)
{
    const float* enc        = (const float*)d_in[0];
    const int*   caps       = (const int*)d_in[1];
    const int*   lens       = (const int*)d_in[2];
    const float* embedding  = (const float*)d_in[3];
    const float* enc_att_w  = (const float*)d_in[4];
    const float* enc_att_b  = (const float*)d_in[5];
    const float* dec_att_w  = (const float*)d_in[6];
    const float* dec_att_b  = (const float*)d_in[7];
    const float* full_att_w = (const float*)d_in[8];
    const float* lstm_wih   = (const float*)d_in[10];
    const float* lstm_whh   = (const float*)d_in[11];
    const float* lstm_bih   = (const float*)d_in[12];
    const float* lstm_bhh   = (const float*)d_in[13];
    const float* init_h_w   = (const float*)d_in[14];
    const float* init_h_b   = (const float*)d_in[15];
    const float* init_c_w   = (const float*)d_in[16];
    const float* init_c_b   = (const float*)d_in[17];
    const float* f_beta_w   = (const float*)d_in[18];
    const float* f_beta_b   = (const float*)d_in[19];
    const float* fc_w       = (const float*)d_in[20];
    const float* fc_b       = (const float*)d_in[21];

    float* out      = (float*)d_out;
    float* out_pred = out;
    float* out_lens = out + (size_t)BB * TT * VV;
    float* out_alph = out_lens + BB;

    cudaFuncSetAttribute(hgemm_k<0>, cudaFuncAttributeMaxDynamicSharedMemorySize, SMEMSZ);
    cudaFuncSetAttribute(hgemm_k<3>, cudaFuncAttributeMaxDynamicSharedMemorySize, SMEMSZ);
    cudaFuncSetAttribute(hgemm_k<4>, cudaFuncAttributeMaxDynamicSharedMemorySize, SMEMSZ);
    cudaFuncSetAttribute(ag2_k, cudaFuncAttributeMaxDynamicSharedMemorySize, SMEMSZ2);
    cudaFuncSetAttribute(gates_cell_k, cudaFuncAttributeMaxDynamicSharedMemorySize, SMEMSZ2);

    cudaStream_t s2;
    cudaStreamCreateWithFlags(&s2, cudaStreamNonBlocking);
    cudaEvent_t evA[TT / 8], evB[TT / 8], evP, evF;
    for (int i = 0; i < TT / 8; i++) {
        cudaEventCreateWithFlags(&evA[i], cudaEventDisableTiming);
        cudaEventCreateWithFlags(&evB[i], cudaEventDisableTiming);
    }
    cudaEventCreateWithFlags(&evP, cudaEventDisableTiming);
    cudaEventCreateWithFlags(&evF, cudaEventDisableTiming);

    __half *p_encb, *p_emb16, *p_xh, *p_hall, *p_mean16, *p_att1;
    __half *p_wag, *p_wg, *p_wtop, *p_wfc, *p_wenc, *p_wih0, *p_wic0;
    float *p_h, *p_c, *p_ag, *p_embW, *p_bag;
    cudaGetSymbolAddress((void**)&p_encb, g_encb);
    cudaGetSymbolAddress((void**)&p_emb16, g_emb16);
    cudaGetSymbolAddress((void**)&p_xh, g_xh);
    cudaGetSymbolAddress((void**)&p_hall, g_hall);
    cudaGetSymbolAddress((void**)&p_mean16, g_mean16);
    cudaGetSymbolAddress((void**)&p_att1, g_att1);
    cudaGetSymbolAddress((void**)&p_wag, g_wag);
    cudaGetSymbolAddress((void**)&p_wg, g_wg);
    cudaGetSymbolAddress((void**)&p_wtop, g_wtop);
    cudaGetSymbolAddress((void**)&p_wfc, g_wfc);
    cudaGetSymbolAddress((void**)&p_wenc, g_wenc);
    cudaGetSymbolAddress((void**)&p_wih0, g_wih0);
    cudaGetSymbolAddress((void**)&p_wic0, g_wic0);
    cudaGetSymbolAddress((void**)&p_h, g_h);
    cudaGetSymbolAddress((void**)&p_c, g_c);
    cudaGetSymbolAddress((void**)&p_ag, g_ag);
    cudaGetSymbolAddress((void**)&p_embW, g_embW);
    cudaGetSymbolAddress((void**)&p_bag, g_bag);

    // capture-legal fork of s2
    cudaEventRecord(evF, 0);
    cudaStreamWaitEvent(s2, evF, 0);

    // s2: embW precompute chain, then prediction-region memset
    cvt_k<<<cgrid(VV * EE), 256, 0, s2>>>(embedding, p_emb16, VV, EE, EE, EE, EE);
    cvt_k<<<cgrid(256 * GG), 256, 0, s2>>>(lstm_wih, p_wtop, 256, GG, GG, GG, GG);
    hgemm_k<0><<<dim3(GG / 128, (VV + 127) / 128), 256, SMEMSZ, s2>>>(p_emb16, EE, p_wtop, GG,
        nullptr, p_embW, nullptr, GG, VV, GG, EE, nullptr, 0);
    cudaEventRecord(evP, s2);
    cudaMemsetAsync(out_pred, 0, (size_t)BB * TT * VV * sizeof(float), s2);

    // stream 0: conversions (+ encoder fp16 copy AND transpose)
    cvt_k<<<cgrid(BB * PP * ENCD), 256>>>(enc, p_encb, BB * PP, ENCD, ENCD, ENCD, ENCD);
    trE_k<<<dim3(ENCD / 32, PP / 32, BB), 256>>>(enc);
    cvt_k<<<cgrid(512 * 512), 256>>>(dec_att_w, p_wag, 512, 512, 512, 768, 512);
    cvt_k<<<cgrid(512 * 256), 256>>>(f_beta_w, p_wag + 512, 512, 256, 256, 768, 256);
    cvt_k<<<cgrid(256 * GG), 256>>>(lstm_wih + (size_t)EE * GG, p_wg, 256, GG, GG, GG, GG);
    cvt_k<<<cgrid(512 * GG), 256>>>(lstm_whh, p_wg + (size_t)256 * GG, 512, GG, GG, GG, GG);
    cvt_k<<<cgrid(512 * VPAD), 256>>>(fc_w, p_wfc, 512, VPAD, VV, VPAD, VV);
    cvt_k<<<cgrid(256 * 512), 256>>>(enc_att_w, p_wenc, 256, 512, 512, 512, 512);
    cvt_k<<<cgrid(256 * 512), 256>>>(init_h_w, p_wih0, 256, 512, 512, 512, 512);
    cvt_k<<<cgrid(256 * 512), 256>>>(init_c_w, p_wic0, 256, 512, 512, 512, 512);
    bag_k<<<3, 256>>>(dec_att_b, f_beta_b);
    mean_k<<<BB, 256>>>(enc);

    // one-time TC GEMMs
    hgemm_k<0><<<dim3(DECD / 128, BB / 128), 256, SMEMSZ>>>(p_mean16, ENCD, p_wih0, DECD,
        init_h_b, p_h, nullptr, DECD, BB, DECD, ENCD, nullptr, 0);
    hgemm_k<0><<<dim3(DECD / 128, BB / 128), 256, SMEMSZ>>>(p_mean16, ENCD, p_wic0, DECD,
        init_c_b, p_c, nullptr, DECD, BB, DECD, ENCD, nullptr, 0);
    h0c_k<<<BB, DECD>>>();
    hgemm_k<4><<<dim3(DECD / 128, (BB * PP) / 128), 256, SMEMSZ>>>(p_encb, ENCD, p_wenc, DECD,
        enc_att_b, nullptr, p_att1, DECD, BB * PP, DECD, ENCD, nullptr, 0);
    lens_k<<<1, BB>>>(lens, out_lens);

    // join s2 precompute (embW needed by gates_cell at t=0)
    cudaStreamWaitEvent(0, evP, 0);

    // timestep loop: 3 launches/step
    for (int t = 0; t < TT; t++) {
        const float* ccur = p_c + (t & 1) * (BB * DECD);
        float*       cnext = p_c + ((t + 1) & 1) * (BB * DECD);

        ag2_k<<<dim3(22, 4), 256, SMEMSZ2>>>();
        attention_k<<<BB, 256>>>(full_att_w, lens, t, out_alph);
        gates_cell_k<<<dim3(16, 4), 256, SMEMSZ2>>>(lstm_bih, lstm_bhh, caps, ccur, cnext, t);

        if ((t & 7) == 7) {
            int c = t >> 3;
            cudaEventRecord(evA[c], 0);
            cudaStreamWaitEvent(s2, evA[c], 0);
            hgemm_k<3><<<dim3(VPAD / 128, 16), 256, SMEMSZ, s2>>>(p_hall, DECD, p_wfc, VPAD,
                fc_b, out_pred, nullptr, VV, BB * TT, VV, DECD, lens, c * 8 * BB);
            cudaEventRecord(evB[c], s2);
        }
    }

    for (int c = 0; c < TT / 8; c++) cudaStreamWaitEvent(0, evB[c], 0);
}